// round 3
// baseline (speedup 1.0000x reference)
#include <cuda_runtime.h>
#include <cstdint>

#define PITCH 68  // smem pitch in words: 68*4=272B, 16B-aligned rows, conflict-avoiding

// ---------------- scratch (device globals; no allocation allowed) ----------------
__device__ float g_Y[8192ULL * 2304];      // QKV output (B*N, 3*H*d): t*768 + h*64 + d
__device__ float g_qgr[384ULL * 256 * 64]; // Q-grassmann  [slab][n][d], slab = b*12+h
__device__ float g_kgr[384ULL * 256 * 64];
__device__ float g_attn[384ULL * 256 * 256]; // dots^2*scale, then (in-place) softmaxed attn
__device__ float g_ao[8192ULL * 768];      // attn@V, (b,n,h,d) flattened

#define FMA16(acc, av, bv)                                                                         \
    acc[0][0] += av.x * bv.x; acc[0][1] += av.x * bv.y; acc[0][2] += av.x * bv.z; acc[0][3] += av.x * bv.w; \
    acc[1][0] += av.y * bv.x; acc[1][1] += av.y * bv.y; acc[1][2] += av.y * bv.z; acc[1][3] += av.y * bv.w; \
    acc[2][0] += av.z * bv.x; acc[2][1] += av.z * bv.y; acc[2][2] += av.z * bv.z; acc[2][3] += av.z * bv.w; \
    acc[3][0] += av.w * bv.x; acc[3][1] += av.w * bv.y; acc[3][2] += av.w * bv.z; acc[3][3] += av.w * bv.w;

// ---------------- C = A @ B^T + bias  (A: MxK rowmajor, B: NxK rowmajor) ----------------
// 64x64 tile, BK=16, 256 threads, 4x4 per thread.
__global__ void gemm_abt(const float* __restrict__ A, const float* __restrict__ B,
                         const float* __restrict__ bias, float* __restrict__ C,
                         int M, int N, int K)
{
    __shared__ float As[16 * PITCH];
    __shared__ float Bs[16 * PITCH];
    const int n0 = blockIdx.x * 64;
    const int m0 = blockIdx.y * 64;
    const int t  = threadIdx.x;
    const int tx = t & 15, ty = t >> 4;
    const int lrow = t >> 2;
    const int lkg  = (t & 3) << 2;
    float acc[4][4] = {};
    for (int k0 = 0; k0 < K; k0 += 16) {
        float4 a = *(const float4*)(A + (size_t)(m0 + lrow) * K + k0 + lkg);
        float4 b = *(const float4*)(B + (size_t)(n0 + lrow) * K + k0 + lkg);
        __syncthreads();
        As[(lkg + 0) * PITCH + lrow] = a.x;
        As[(lkg + 1) * PITCH + lrow] = a.y;
        As[(lkg + 2) * PITCH + lrow] = a.z;
        As[(lkg + 3) * PITCH + lrow] = a.w;
        Bs[(lkg + 0) * PITCH + lrow] = b.x;
        Bs[(lkg + 1) * PITCH + lrow] = b.y;
        Bs[(lkg + 2) * PITCH + lrow] = b.z;
        Bs[(lkg + 3) * PITCH + lrow] = b.w;
        __syncthreads();
#pragma unroll
        for (int kk = 0; kk < 16; ++kk) {
            float4 av = *(const float4*)(As + kk * PITCH + ty * 4);
            float4 bv = *(const float4*)(Bs + kk * PITCH + tx * 4);
            FMA16(acc, av, bv)
        }
    }
    float4 bb = *(const float4*)(bias + n0 + tx * 4);
#pragma unroll
    for (int r = 0; r < 4; ++r) {
        float4 o;
        o.x = acc[r][0] + bb.x; o.y = acc[r][1] + bb.y;
        o.z = acc[r][2] + bb.z; o.w = acc[r][3] + bb.w;
        *(float4*)(C + (size_t)(m0 + ty * 4 + r) * N + n0 + tx * 4) = o;
    }
}

// ---------------- per-slab Householder QR (LAPACK convention), Q via org2r ----------------
// One 256-thread block per slab (b,h). A held column-major in smem, pitch 257.
// Reads q/k directly out of g_Y with row stride 2304.
__global__ void qr_kernel(const float* __restrict__ Y, float* __restrict__ Qout, int coloff)
{
    extern __shared__ float A[];   // 64 * 257 floats
    __shared__ float tauv[64];
    __shared__ float red[8];
    __shared__ float s_tau, s_inv;
    const int slab = blockIdx.x;
    const int b = slab / 12, h = slab % 12;
    const float* src = Y + (size_t)b * 256 * 2304 + coloff + h * 64;
    const int t = threadIdx.x;
    const int lane = t & 31, wid = t >> 5;

    {   // load 256x64, store transposed (column-major)
        const int rloc = t >> 4, dg = (t & 15) << 2;
#pragma unroll
        for (int it = 0; it < 16; ++it) {
            int n = it * 16 + rloc;
            float4 v = *(const float4*)(src + (size_t)n * 2304 + dg);
            A[(dg + 0) * 257 + n] = v.x;
            A[(dg + 1) * 257 + n] = v.y;
            A[(dg + 2) * 257 + n] = v.z;
            A[(dg + 3) * 257 + n] = v.w;
        }
    }
    __syncthreads();

    // -------- geqf2 (unblocked Householder) --------
    for (int j = 0; j < 64; ++j) {
        float p = 0.f;
        if (t > j) { float x = A[j * 257 + t]; p = x * x; }
#pragma unroll
        for (int o = 16; o; o >>= 1) p += __shfl_xor_sync(0xffffffffu, p, o);
        if (lane == 0) red[wid] = p;
        __syncthreads();
        if (t == 0) {
            float xn2 = red[0] + red[1] + red[2] + red[3] + red[4] + red[5] + red[6] + red[7];
            float alpha = A[j * 257 + j];
            float tau, inv;
            if (xn2 <= 0.f) { tau = 0.f; inv = 0.f; }
            else {
                float nrm  = sqrtf(alpha * alpha + xn2);
                float beta = (alpha >= 0.f) ? -nrm : nrm;  // LAPACK dlarfg sign
                tau = (beta - alpha) / beta;
                inv = 1.f / (alpha - beta);
            }
            tauv[j] = tau; s_tau = tau; s_inv = inv;
        }
        __syncthreads();
        float tau = s_tau;
        if (t > j) A[j * 257 + t] *= s_inv;   // v (v0=1 implicit)
        __syncthreads();
        float vr[8];
#pragma unroll
        for (int r = 0; r < 8; ++r) {
            int i = j + lane + 32 * r;
            vr[r] = (i < 256) ? ((i == j) ? 1.f : A[j * 257 + i]) : 0.f;
        }
        for (int k = j + 1 + wid; k < 64; k += 8) {
            float s = 0.f, ar[8];
#pragma unroll
            for (int r = 0; r < 8; ++r) {
                int i = j + lane + 32 * r;
                ar[r] = (i < 256) ? A[k * 257 + i] : 0.f;
                s += vr[r] * ar[r];
            }
#pragma unroll
            for (int o = 16; o; o >>= 1) s += __shfl_xor_sync(0xffffffffu, s, o);
            float ts = tau * s;
#pragma unroll
            for (int r = 0; r < 8; ++r) {
                int i = j + lane + 32 * r;
                if (i < 256) A[k * 257 + i] = ar[r] - ts * vr[r];
            }
        }
        __syncthreads();
    }

    // -------- org2r: form Q in place (backward accumulation) --------
    for (int j = 63; j >= 0; --j) {
        float tau = tauv[j];
        float vr[8];
#pragma unroll
        for (int r = 0; r < 8; ++r) {
            int i = j + lane + 32 * r;
            vr[r] = (i < 256) ? ((i == j) ? 1.f : A[j * 257 + i]) : 0.f;
        }
        for (int k = j + 1 + wid; k < 64; k += 8) {
            float s = 0.f, ar[8];
#pragma unroll
            for (int r = 0; r < 8; ++r) {
                int i = j + lane + 32 * r;
                ar[r] = (i < 256) ? A[k * 257 + i] : 0.f;
                s += vr[r] * ar[r];
            }
#pragma unroll
            for (int o = 16; o; o >>= 1) s += __shfl_xor_sync(0xffffffffu, s, o);
            float ts = tau * s;
#pragma unroll
            for (int r = 0; r < 8; ++r) {
                int i = j + lane + 32 * r;
                if (i < 256) A[k * 257 + i] = ar[r] - ts * vr[r];
            }
        }
        __syncthreads();
        {
            float val;
            if (t < j)       val = 0.f;
            else if (t == j) val = 1.f - tau;
            else             val = -tau * A[j * 257 + t];
            A[j * 257 + t] = val;
        }
        __syncthreads();
    }

    {   // store Q packed [slab][n][d]
        const int rloc = t >> 4, dg = (t & 15) << 2;
#pragma unroll
        for (int it = 0; it < 16; ++it) {
            int n = it * 16 + rloc;
            float4 v;
            v.x = A[(dg + 0) * 257 + n];
            v.y = A[(dg + 1) * 257 + n];
            v.z = A[(dg + 2) * 257 + n];
            v.w = A[(dg + 3) * 257 + n];
            *(float4*)(Qout + ((size_t)slab * 256 + n) * 64 + dg) = v;
        }
    }
}

// ---------------- per-slab dots = Qgr @ Kgr^T, fused square * scale ----------------
__global__ void dots_kernel(const float* __restrict__ Qg, const float* __restrict__ Kg,
                            float* __restrict__ G, const float* __restrict__ scale_p)
{
    __shared__ float As[64 * PITCH];
    __shared__ float Bs[64 * PITCH];
    const int slab = blockIdx.z;
    const int m0 = blockIdx.x * 64, n0 = blockIdx.y * 64;
    const float* Ap = Qg + (size_t)slab * 256 * 64;
    const float* Bp = Kg + (size_t)slab * 256 * 64;
    const int t = threadIdx.x;
    const int tx = t & 15, ty = t >> 4;
    const int rloc = t >> 4, dg = (t & 15) << 2;
#pragma unroll
    for (int it = 0; it < 4; ++it) {
        int r = it * 16 + rloc;
        float4 a = *(const float4*)(Ap + (size_t)(n0 + r) * 64 + dg);
        float4 b = *(const float4*)(Bp + (size_t)(m0 + r) * 64 + dg);
        As[(dg + 0) * PITCH + r] = a.x; As[(dg + 1) * PITCH + r] = a.y;
        As[(dg + 2) * PITCH + r] = a.z; As[(dg + 3) * PITCH + r] = a.w;
        Bs[(dg + 0) * PITCH + r] = b.x; Bs[(dg + 1) * PITCH + r] = b.y;
        Bs[(dg + 2) * PITCH + r] = b.z; Bs[(dg + 3) * PITCH + r] = b.w;
    }
    __syncthreads();
    float acc[4][4] = {};
#pragma unroll 8
    for (int kk = 0; kk < 64; ++kk) {
        float4 av = *(const float4*)(As + kk * PITCH + ty * 4);
        float4 bv = *(const float4*)(Bs + kk * PITCH + tx * 4);
        FMA16(acc, av, bv)
    }
    float sc = *scale_p;
#pragma unroll
    for (int r = 0; r < 4; ++r) {
        float4 o;
        o.x = acc[r][0] * acc[r][0] * sc;
        o.y = acc[r][1] * acc[r][1] * sc;
        o.z = acc[r][2] * acc[r][2] * sc;
        o.w = acc[r][3] * acc[r][3] * sc;
        *(float4*)(G + ((size_t)slab * 256 + n0 + ty * 4 + r) * 256 + m0 + tx * 4) = o;
    }
}

// ---------------- cross-head 1x1-conv mix + softmax, in place on G ----------------
// Block per (b,n); 12 warps; warp o: mixed[o,m] = sum_h w2[o,h]*g[h,m] + cb[o]; softmax over m.
__global__ void mix_softmax(float* __restrict__ G, const float* __restrict__ cw,
                            const float* __restrict__ cbg)
{
    __shared__ float gsm[12 * 256];
    __shared__ float w2[144];
    __shared__ float cb[12];
    const int n = blockIdx.x, b = blockIdx.y;
    const int t = threadIdx.x;          // 384
    const int lane = t & 31, wo = t >> 5;
    if (t < 144) { int o = t / 12, h = t % 12; w2[t] = cw[o * 24 + h] + cw[o * 24 + 12 + h]; }
    if (t < 12) cb[t] = cbg[t];
    {
        float* dstp = gsm + wo * 256;
        const float* srcp = G + ((size_t)(b * 12 + wo) * 256 + n) * 256;
        *(float4*)(dstp + lane * 4)       = *(const float4*)(srcp + lane * 4);
        *(float4*)(dstp + 128 + lane * 4) = *(const float4*)(srcp + 128 + lane * 4);
    }
    __syncthreads();
    float vals[8];
    float mx = -3.4e38f;
#pragma unroll
    for (int r = 0; r < 8; ++r) {
        int m = lane + 32 * r;
        float s = cb[wo];
#pragma unroll
        for (int h = 0; h < 12; ++h) s += w2[wo * 12 + h] * gsm[h * 256 + m];
        vals[r] = s;
        mx = fmaxf(mx, s);
    }
#pragma unroll
    for (int o = 16; o; o >>= 1) mx = fmaxf(mx, __shfl_xor_sync(0xffffffffu, mx, o));
    float sum = 0.f;
#pragma unroll
    for (int r = 0; r < 8; ++r) { vals[r] = expf(vals[r] - mx); sum += vals[r]; }
#pragma unroll
    for (int o = 16; o; o >>= 1) sum += __shfl_xor_sync(0xffffffffu, sum, o);
    float inv = 1.f / sum;
    float* dst = G + ((size_t)(b * 12 + wo) * 256 + n) * 256;
#pragma unroll
    for (int r = 0; r < 8; ++r) dst[lane + 32 * r] = vals[r] * inv;
}

// ---------------- out_h = attn @ v  (v read strided from g_Y), write (b,n,h,d) ----------------
__global__ void attnv_kernel(const float* __restrict__ Attn, const float* __restrict__ Y,
                             float* __restrict__ AO)
{
    __shared__ float As[32 * PITCH];  // [m][n] transposed
    __shared__ float Bs[32 * 64];     // [m][d]
    const int slab = blockIdx.y;
    const int b = slab / 12, h = slab % 12;
    const int n0 = blockIdx.x * 64;
    const float* Ap = Attn + (size_t)slab * 256 * 256;
    const float* Vp = Y + (size_t)b * 256 * 2304 + 1536 + h * 64;
    const int t = threadIdx.x;
    const int tx = t & 15, ty = t >> 4;
    float acc[4][4] = {};
    for (int m0 = 0; m0 < 256; m0 += 32) {
        const int ar = t >> 2, ag = (t & 3) << 2;
        float4 a0 = *(const float4*)(Ap + (size_t)(n0 + ar) * 256 + m0 + ag);
        float4 a1 = *(const float4*)(Ap + (size_t)(n0 + ar) * 256 + m0 + 16 + ag);
        const int br = t >> 4, bg = (t & 15) << 2;
        float4 b0 = *(const float4*)(Vp + (size_t)(m0 + br) * 2304 + bg);
        float4 b1 = *(const float4*)(Vp + (size_t)(m0 + 16 + br) * 2304 + bg);
        __syncthreads();
        As[(ag + 0) * PITCH + ar] = a0.x; As[(ag + 1) * PITCH + ar] = a0.y;
        As[(ag + 2) * PITCH + ar] = a0.z; As[(ag + 3) * PITCH + ar] = a0.w;
        As[(ag + 16) * PITCH + ar] = a1.x; As[(ag + 17) * PITCH + ar] = a1.y;
        As[(ag + 18) * PITCH + ar] = a1.z; As[(ag + 19) * PITCH + ar] = a1.w;
        *(float4*)(Bs + br * 64 + bg)        = b0;
        *(float4*)(Bs + (br + 16) * 64 + bg) = b1;
        __syncthreads();
#pragma unroll
        for (int kk = 0; kk < 32; ++kk) {
            float4 av = *(const float4*)(As + kk * PITCH + ty * 4);
            float4 bv = *(const float4*)(Bs + kk * 64 + tx * 4);
            FMA16(acc, av, bv)
        }
    }
#pragma unroll
    for (int r = 0; r < 4; ++r) {
        float4 o;
        o.x = acc[r][0]; o.y = acc[r][1]; o.z = acc[r][2]; o.w = acc[r][3];
        *(float4*)(AO + (size_t)(b * 256 + n0 + ty * 4 + r) * 768 + h * 64 + tx * 4) = o;
    }
}

// ---------------- launch ----------------
extern "C" void kernel_launch(void* const* d_in, const int* in_sizes, int n_in,
                              void* d_out, int out_size)
{
    (void)in_sizes; (void)n_in; (void)out_size;
    const float* x    = (const float*)d_in[0];
    const float* qkvw = (const float*)d_in[1];
    const float* qkvb = (const float*)d_in[2];
    const float* gsc  = (const float*)d_in[3];
    const float* cw   = (const float*)d_in[4];
    const float* cb   = (const float*)d_in[5];
    const float* pw   = (const float*)d_in[6];
    const float* pb   = (const float*)d_in[7];
    float* out = (float*)d_out;

    float *Y, *qgr, *kgr, *attn, *ao;
    cudaGetSymbolAddress((void**)&Y, g_Y);
    cudaGetSymbolAddress((void**)&qgr, g_qgr);
    cudaGetSymbolAddress((void**)&kgr, g_kgr);
    cudaGetSymbolAddress((void**)&attn, g_attn);
    cudaGetSymbolAddress((void**)&ao, g_ao);

    cudaFuncSetAttribute(qr_kernel, cudaFuncAttributeMaxDynamicSharedMemorySize, 64 * 257 * 4);

    // 1) QKV: Y = x @ qkv_w^T + qkv_b      (8192 x 2304, K=768)
    gemm_abt<<<dim3(2304 / 64, 8192 / 64), 256>>>(x, qkvw, qkvb, Y, 8192, 2304, 768);
    // 2) Householder QR per (b,h) slab for q and k
    qr_kernel<<<384, 256, 64 * 257 * 4>>>(Y, qgr, 0);
    qr_kernel<<<384, 256, 64 * 257 * 4>>>(Y, kgr, 768);
    // 3) dots^2 * scale per slab
    dots_kernel<<<dim3(4, 4, 384), 256>>>(qgr, kgr, attn, gsc);
    // 4) cross-head mix + softmax (in place)
    mix_softmax<<<dim3(256, 32), 384>>>(attn, cw, cb);
    // 5) attn @ v  -> (b,n,h*64+d)
    attnv_kernel<<<dim3(4, 384), 256>>>(attn, Y, ao);
    // 6) proj: out = ao @ proj_w^T + proj_b
    gemm_abt<<<dim3(768 / 64, 8192 / 64), 256>>>(ao, pw, pb, out, 8192, 768, 768);
}

// round 5
// speedup vs baseline: 1.1331x; 1.1331x over previous
#include <cuda_runtime.h>
#include <cstdint>

#define PITCH 68   // legacy pitch for attnv smem
#define TP 132     // 128-wide tile pitch (words): 16B-aligned, mod-4 == 0 for LDS.128

// ---------------- scratch (device globals; no allocation allowed) ----------------
__device__ float g_Y[8192ULL * 2304];      // QKV output (B*N, 3*H*d): t*768 + h*64 + d
__device__ float g_qgr[384ULL * 256 * 64]; // Q-grassmann  [slab][n][d], slab = b*12+h
__device__ float g_kgr[384ULL * 256 * 64];
__device__ float g_attn[384ULL * 256 * 256]; // dots^2*scale, then (in-place) softmaxed attn
__device__ float g_ao[8192ULL * 768];      // attn@V, (b,n,h,d) flattened

#define FMA16(acc, av, bv)                                                                         \
    acc[0][0] += av.x * bv.x; acc[0][1] += av.x * bv.y; acc[0][2] += av.x * bv.z; acc[0][3] += av.x * bv.w; \
    acc[1][0] += av.y * bv.x; acc[1][1] += av.y * bv.y; acc[1][2] += av.y * bv.z; acc[1][3] += av.y * bv.w; \
    acc[2][0] += av.z * bv.x; acc[2][1] += av.z * bv.y; acc[2][2] += av.z * bv.z; acc[2][3] += av.z * bv.w; \
    acc[3][0] += av.w * bv.x; acc[3][1] += av.w * bv.y; acc[3][2] += av.w * bv.z; acc[3][3] += av.w * bv.w;

// ================= 128x128x16 SIMT GEMM core: 8x8 per thread =================
// Shared inner loop for gemm128 / dots128. As/Bs are [BK][128] with pitch TP.
#define G128_LOAD_STAGE(Ap, Bp, k0)                                                                \
    float4 a0 = *(const float4*)(Ap + (k0));                                                       \
    float4 a1 = *(const float4*)(Ap + (k0) + 4);                                                   \
    float4 b0 = *(const float4*)(Bp + (k0));                                                       \
    float4 b1 = *(const float4*)(Bp + (k0) + 4);                                                   \
    __syncthreads();                                                                               \
    As[(lk + 0) * TP + lr] = a0.x; As[(lk + 1) * TP + lr] = a0.y;                                  \
    As[(lk + 2) * TP + lr] = a0.z; As[(lk + 3) * TP + lr] = a0.w;                                  \
    As[(lk + 4) * TP + lr] = a1.x; As[(lk + 5) * TP + lr] = a1.y;                                  \
    As[(lk + 6) * TP + lr] = a1.z; As[(lk + 7) * TP + lr] = a1.w;                                  \
    Bs[(lk + 0) * TP + lr] = b0.x; Bs[(lk + 1) * TP + lr] = b0.y;                                  \
    Bs[(lk + 2) * TP + lr] = b0.z; Bs[(lk + 3) * TP + lr] = b0.w;                                  \
    Bs[(lk + 4) * TP + lr] = b1.x; Bs[(lk + 5) * TP + lr] = b1.y;                                  \
    Bs[(lk + 6) * TP + lr] = b1.z; Bs[(lk + 7) * TP + lr] = b1.w;                                  \
    __syncthreads();

#define G128_COMPUTE()                                                                             \
    _Pragma("unroll")                                                                              \
    for (int kk = 0; kk < 16; ++kk) {                                                              \
        float4 av0 = *(const float4*)(As + kk * TP + ty * 8);                                      \
        float4 av1 = *(const float4*)(As + kk * TP + ty * 8 + 4);                                  \
        float4 bv0 = *(const float4*)(Bs + kk * TP + tx * 8);                                      \
        float4 bv1 = *(const float4*)(Bs + kk * TP + tx * 8 + 4);                                  \
        float ar[8] = {av0.x, av0.y, av0.z, av0.w, av1.x, av1.y, av1.z, av1.w};                    \
        float br[8] = {bv0.x, bv0.y, bv0.z, bv0.w, bv1.x, bv1.y, bv1.z, bv1.w};                    \
        _Pragma("unroll")                                                                          \
        for (int i = 0; i < 8; ++i)                                                                \
            _Pragma("unroll")                                                                      \
            for (int j = 0; j < 8; ++j) acc[i][j] += ar[i] * br[j];                                \
    }

// ---------------- C = A @ B^T + bias  (A: MxK rowmajor, B: NxK rowmajor) ----------------
__global__ __launch_bounds__(256, 2) void gemm128(const float* __restrict__ A,
                                                  const float* __restrict__ B,
                                                  const float* __restrict__ bias,
                                                  float* __restrict__ C,
                                                  int M, int N, int K)
{
    __shared__ float As[16 * TP];
    __shared__ float Bs[16 * TP];
    const int n0 = blockIdx.x * 128;
    const int m0 = blockIdx.y * 128;
    const int t  = threadIdx.x;
    const int tx = t & 15, ty = t >> 4;
    const int lr = t >> 1, lk = (t & 1) * 8;
    const float* Ap = A + (size_t)(m0 + lr) * K + lk;
    const float* Bp = B + (size_t)(n0 + lr) * K + lk;
    float acc[8][8] = {};
    for (int k0 = 0; k0 < K; k0 += 16) {
        G128_LOAD_STAGE(Ap, Bp, k0)
        G128_COMPUTE()
    }
    float4 bb0 = *(const float4*)(bias + n0 + tx * 8);
    float4 bb1 = *(const float4*)(bias + n0 + tx * 8 + 4);
#pragma unroll
    for (int i = 0; i < 8; ++i) {
        float4 o0, o1;
        o0.x = acc[i][0] + bb0.x; o0.y = acc[i][1] + bb0.y;
        o0.z = acc[i][2] + bb0.z; o0.w = acc[i][3] + bb0.w;
        o1.x = acc[i][4] + bb1.x; o1.y = acc[i][5] + bb1.y;
        o1.z = acc[i][6] + bb1.z; o1.w = acc[i][7] + bb1.w;
        float* cp = C + (size_t)(m0 + ty * 8 + i) * N + n0 + tx * 8;
        *(float4*)cp       = o0;
        *(float4*)(cp + 4) = o1;
    }
}

// ---------------- per-slab dots = Qgr @ Kgr^T, fused square * scale ----------------
__global__ __launch_bounds__(256, 2) void dots128(const float* __restrict__ Qg,
                                                  const float* __restrict__ Kg,
                                                  float* __restrict__ G,
                                                  const float* __restrict__ scale_p)
{
    __shared__ float As[16 * TP];
    __shared__ float Bs[16 * TP];
    const int slab = blockIdx.z;
    const int m0 = blockIdx.x * 128;  // col (m index over kgr rows)
    const int n0 = blockIdx.y * 128;  // row (n index over qgr rows)
    const int t  = threadIdx.x;
    const int tx = t & 15, ty = t >> 4;
    const int lr = t >> 1, lk = (t & 1) * 8;
    const float* Ap = Qg + (size_t)slab * 256 * 64 + (size_t)(n0 + lr) * 64 + lk;
    const float* Bp = Kg + (size_t)slab * 256 * 64 + (size_t)(m0 + lr) * 64 + lk;
    float acc[8][8] = {};
    for (int k0 = 0; k0 < 64; k0 += 16) {
        G128_LOAD_STAGE(Ap, Bp, k0)
        G128_COMPUTE()
    }
    const float sc = *scale_p;
#pragma unroll
    for (int i = 0; i < 8; ++i) {
        float4 o0, o1;
        o0.x = acc[i][0] * acc[i][0] * sc; o0.y = acc[i][1] * acc[i][1] * sc;
        o0.z = acc[i][2] * acc[i][2] * sc; o0.w = acc[i][3] * acc[i][3] * sc;
        o1.x = acc[i][4] * acc[i][4] * sc; o1.y = acc[i][5] * acc[i][5] * sc;
        o1.z = acc[i][6] * acc[i][6] * sc; o1.w = acc[i][7] * acc[i][7] * sc;
        float* gp = G + ((size_t)slab * 256 + n0 + ty * 8 + i) * 256 + m0 + tx * 8;
        *(float4*)gp       = o0;
        *(float4*)(gp + 4) = o1;
    }
}

// ---------------- per-slab Householder QR (LAPACK convention), Q via org2r ----------------
// 768 blocks: bid<384 -> q (coloff 0), else k (coloff 768). One 256-thread block per slab.
__global__ void qr_kernel(const float* __restrict__ Y, float* __restrict__ Qq,
                          float* __restrict__ Qk)
{
    extern __shared__ float A[];   // 64 * 257 floats
    __shared__ float tauv[64];
    __shared__ float red[8];
    __shared__ float s_tau, s_inv;
    const int bid = blockIdx.x;
    const int slab = (bid < 384) ? bid : bid - 384;
    const int coloff = (bid < 384) ? 0 : 768;
    float* Qout = (bid < 384) ? Qq : Qk;
    const int b = slab / 12, h = slab % 12;
    const float* src = Y + (size_t)b * 256 * 2304 + coloff + h * 64;
    const int t = threadIdx.x;
    const int lane = t & 31, wid = t >> 5;

    {   // load 256x64, store transposed (column-major)
        const int rloc = t >> 4, dg = (t & 15) << 2;
#pragma unroll
        for (int it = 0; it < 16; ++it) {
            int n = it * 16 + rloc;
            float4 v = *(const float4*)(src + (size_t)n * 2304 + dg);
            A[(dg + 0) * 257 + n] = v.x;
            A[(dg + 1) * 257 + n] = v.y;
            A[(dg + 2) * 257 + n] = v.z;
            A[(dg + 3) * 257 + n] = v.w;
        }
    }
    __syncthreads();

    // -------- geqf2 (unblocked Householder) --------
    for (int j = 0; j < 64; ++j) {
        float p = 0.f;
        if (t > j) { float x = A[j * 257 + t]; p = x * x; }
#pragma unroll
        for (int o = 16; o; o >>= 1) p += __shfl_xor_sync(0xffffffffu, p, o);
        if (lane == 0) red[wid] = p;
        __syncthreads();
        if (t == 0) {
            float xn2 = red[0] + red[1] + red[2] + red[3] + red[4] + red[5] + red[6] + red[7];
            float alpha = A[j * 257 + j];
            float tau, inv;
            if (xn2 <= 0.f) { tau = 0.f; inv = 0.f; }
            else {
                float nrm  = sqrtf(alpha * alpha + xn2);
                float beta = (alpha >= 0.f) ? -nrm : nrm;  // LAPACK dlarfg sign
                tau = (beta - alpha) / beta;
                inv = 1.f / (alpha - beta);
            }
            tauv[j] = tau; s_tau = tau; s_inv = inv;
        }
        __syncthreads();
        float tau = s_tau;
        if (t > j) A[j * 257 + t] *= s_inv;   // v (v0=1 implicit)
        __syncthreads();
        float vr[8];
#pragma unroll
        for (int r = 0; r < 8; ++r) {
            int i = j + lane + 32 * r;
            vr[r] = (i < 256) ? ((i == j) ? 1.f : A[j * 257 + i]) : 0.f;
        }
        for (int k = j + 1 + wid; k < 64; k += 8) {
            float s = 0.f, ar[8];
#pragma unroll
            for (int r = 0; r < 8; ++r) {
                int i = j + lane + 32 * r;
                ar[r] = (i < 256) ? A[k * 257 + i] : 0.f;
                s += vr[r] * ar[r];
            }
#pragma unroll
            for (int o = 16; o; o >>= 1) s += __shfl_xor_sync(0xffffffffu, s, o);
            float ts = tau * s;
#pragma unroll
            for (int r = 0; r < 8; ++r) {
                int i = j + lane + 32 * r;
                if (i < 256) A[k * 257 + i] = ar[r] - ts * vr[r];
            }
        }
        __syncthreads();
    }

    // -------- org2r: form Q in place (backward accumulation) --------
    for (int j = 63; j >= 0; --j) {
        float tau = tauv[j];
        float vr[8];
#pragma unroll
        for (int r = 0; r < 8; ++r) {
            int i = j + lane + 32 * r;
            vr[r] = (i < 256) ? ((i == j) ? 1.f : A[j * 257 + i]) : 0.f;
        }
        for (int k = j + 1 + wid; k < 64; k += 8) {
            float s = 0.f, ar[8];
#pragma unroll
            for (int r = 0; r < 8; ++r) {
                int i = j + lane + 32 * r;
                ar[r] = (i < 256) ? A[k * 257 + i] : 0.f;
                s += vr[r] * ar[r];
            }
#pragma unroll
            for (int o = 16; o; o >>= 1) s += __shfl_xor_sync(0xffffffffu, s, o);
            float ts = tau * s;
#pragma unroll
            for (int r = 0; r < 8; ++r) {
                int i = j + lane + 32 * r;
                if (i < 256) A[k * 257 + i] = ar[r] - ts * vr[r];
            }
        }
        __syncthreads();
        {
            float val;
            if (t < j)       val = 0.f;
            else if (t == j) val = 1.f - tau;
            else             val = -tau * A[j * 257 + t];
            A[j * 257 + t] = val;
        }
        __syncthreads();
    }

    {   // store Q packed [slab][n][d]
        const int rloc = t >> 4, dg = (t & 15) << 2;
#pragma unroll
        for (int it = 0; it < 16; ++it) {
            int n = it * 16 + rloc;
            float4 v;
            v.x = A[(dg + 0) * 257 + n];
            v.y = A[(dg + 1) * 257 + n];
            v.z = A[(dg + 2) * 257 + n];
            v.w = A[(dg + 3) * 257 + n];
            *(float4*)(Qout + ((size_t)slab * 256 + n) * 64 + dg) = v;
        }
    }
}

// ---------------- cross-head 1x1-conv mix + softmax, in place on G ----------------
__global__ void mix_softmax(float* __restrict__ G, const float* __restrict__ cw,
                            const float* __restrict__ cbg)
{
    __shared__ float gsm[12 * 256];
    __shared__ float w2[144];
    __shared__ float cb[12];
    const int n = blockIdx.x, b = blockIdx.y;
    const int t = threadIdx.x;          // 384
    const int lane = t & 31, wo = t >> 5;
    if (t < 144) { int o = t / 12, h = t % 12; w2[t] = cw[o * 24 + h] + cw[o * 24 + 12 + h]; }
    if (t < 12) cb[t] = cbg[t];
    {
        float* dstp = gsm + wo * 256;
        const float* srcp = G + ((size_t)(b * 12 + wo) * 256 + n) * 256;
        *(float4*)(dstp + lane * 4)       = *(const float4*)(srcp + lane * 4);
        *(float4*)(dstp + 128 + lane * 4) = *(const float4*)(srcp + 128 + lane * 4);
    }
    __syncthreads();
    float vals[8];
    float mx = -3.4e38f;
#pragma unroll
    for (int r = 0; r < 8; ++r) {
        int m = lane + 32 * r;
        float s = cb[wo];
#pragma unroll
        for (int h = 0; h < 12; ++h) s += w2[wo * 12 + h] * gsm[h * 256 + m];
        vals[r] = s;
        mx = fmaxf(mx, s);
    }
#pragma unroll
    for (int o = 16; o; o >>= 1) mx = fmaxf(mx, __shfl_xor_sync(0xffffffffu, mx, o));
    float sum = 0.f;
#pragma unroll
    for (int r = 0; r < 8; ++r) { vals[r] = expf(vals[r] - mx); sum += vals[r]; }
#pragma unroll
    for (int o = 16; o; o >>= 1) sum += __shfl_xor_sync(0xffffffffu, sum, o);
    float inv = 1.f / sum;
    float* dst = G + ((size_t)(b * 12 + wo) * 256 + n) * 256;
#pragma unroll
    for (int r = 0; r < 8; ++r) dst[lane + 32 * r] = vals[r] * inv;
}

// ---------------- out_h = attn @ v  (v read strided from g_Y), write (b,n,h,d) ----------------
__global__ void attnv_kernel(const float* __restrict__ Attn, const float* __restrict__ Y,
                             float* __restrict__ AO)
{
    __shared__ float As[32 * PITCH];  // [m][n] transposed
    __shared__ float Bs[32 * 64];     // [m][d]
    const int slab = blockIdx.y;
    const int b = slab / 12, h = slab % 12;
    const int n0 = blockIdx.x * 64;
    const float* Ap = Attn + (size_t)slab * 256 * 256;
    const float* Vp = Y + (size_t)b * 256 * 2304 + 1536 + h * 64;
    const int t = threadIdx.x;
    const int tx = t & 15, ty = t >> 4;
    float acc[4][4] = {};
    for (int m0 = 0; m0 < 256; m0 += 32) {
        const int ar = t >> 2, ag = (t & 3) << 2;
        float4 a0 = *(const float4*)(Ap + (size_t)(n0 + ar) * 256 + m0 + ag);
        float4 a1 = *(const float4*)(Ap + (size_t)(n0 + ar) * 256 + m0 + 16 + ag);
        const int br = t >> 4, bg = (t & 15) << 2;
        float4 b0 = *(const float4*)(Vp + (size_t)(m0 + br) * 2304 + bg);
        float4 b1 = *(const float4*)(Vp + (size_t)(m0 + 16 + br) * 2304 + bg);
        __syncthreads();
        As[(ag + 0) * PITCH + ar] = a0.x; As[(ag + 1) * PITCH + ar] = a0.y;
        As[(ag + 2) * PITCH + ar] = a0.z; As[(ag + 3) * PITCH + ar] = a0.w;
        As[(ag + 16) * PITCH + ar] = a1.x; As[(ag + 17) * PITCH + ar] = a1.y;
        As[(ag + 18) * PITCH + ar] = a1.z; As[(ag + 19) * PITCH + ar] = a1.w;
        *(float4*)(Bs + br * 64 + bg)        = b0;
        *(float4*)(Bs + (br + 16) * 64 + bg) = b1;
        __syncthreads();
#pragma unroll
        for (int kk = 0; kk < 32; ++kk) {
            float4 av = *(const float4*)(As + kk * PITCH + ty * 4);
            float4 bv = *(const float4*)(Bs + kk * 64 + tx * 4);
            FMA16(acc, av, bv)
        }
    }
#pragma unroll
    for (int r = 0; r < 4; ++r) {
        float4 o;
        o.x = acc[r][0]; o.y = acc[r][1]; o.z = acc[r][2]; o.w = acc[r][3];
        *(float4*)(AO + (size_t)(b * 256 + n0 + ty * 4 + r) * 768 + h * 64 + tx * 4) = o;
    }
}

// ---------------- launch ----------------
extern "C" void kernel_launch(void* const* d_in, const int* in_sizes, int n_in,
                              void* d_out, int out_size)
{
    (void)in_sizes; (void)n_in; (void)out_size;
    const float* x    = (const float*)d_in[0];
    const float* qkvw = (const float*)d_in[1];
    const float* qkvb = (const float*)d_in[2];
    const float* gsc  = (const float*)d_in[3];
    const float* cw   = (const float*)d_in[4];
    const float* cb   = (const float*)d_in[5];
    const float* pw   = (const float*)d_in[6];
    const float* pb   = (const float*)d_in[7];
    float* out = (float*)d_out;

    float *Y, *qgr, *kgr, *attn, *ao;
    cudaGetSymbolAddress((void**)&Y, g_Y);
    cudaGetSymbolAddress((void**)&qgr, g_qgr);
    cudaGetSymbolAddress((void**)&kgr, g_kgr);
    cudaGetSymbolAddress((void**)&attn, g_attn);
    cudaGetSymbolAddress((void**)&ao, g_ao);

    cudaFuncSetAttribute(qr_kernel, cudaFuncAttributeMaxDynamicSharedMemorySize, 64 * 257 * 4);

    // 1) QKV: Y = x @ qkv_w^T + qkv_b      (8192 x 2304, K=768)
    gemm128<<<dim3(2304 / 128, 8192 / 128), 256>>>(x, qkvw, qkvb, Y, 8192, 2304, 768);
    // 2) Householder QR per (b,h) slab for q AND k in one launch (768 blocks)
    qr_kernel<<<768, 256, 64 * 257 * 4>>>(Y, qgr, kgr);
    // 3) dots^2 * scale per slab (128x128 tiles)
    dots128<<<dim3(2, 2, 384), 256>>>(qgr, kgr, attn, gsc);
    // 4) cross-head mix + softmax (in place)
    mix_softmax<<<dim3(256, 32), 384>>>(attn, cw, cb);
    // 5) attn @ v  -> (b,n,h*64+d)
    attnv_kernel<<<dim3(4, 384), 256>>>(attn, Y, ao);
    // 6) proj: out = ao @ proj_w^T + proj_b
    gemm128<<<dim3(768 / 128, 8192 / 128), 256>>>(ao, pw, pb, out, 8192, 768, 768);
}

// round 7
// speedup vs baseline: 1.1481x; 1.0132x over previous
#include <cuda_runtime.h>
#include <cstdint>

#define TP 132     // 128-wide tile pitch (words)
#define VP 68      // 64-wide tile pitch (words)

// ---------------- scratch (device globals; no allocation allowed) ----------------
__device__ float g_Y[8192ULL * 2304];      // QKV output (B*N, 3*H*d): t*768 + h*64 + d
__device__ float g_qgr[384ULL * 256 * 64]; // Q-grassmann  [slab][n][d], slab = b*12+h
__device__ float g_kgr[384ULL * 256 * 64];
__device__ float g_attn[384ULL * 256 * 256]; // dots^2*scale, then (in-place) softmaxed attn
__device__ float g_ao[8192ULL * 768];      // attn@V, (b,n,h,d) flattened

// ================= 128x128x16 SIMT GEMM core: 8x8 per thread, double-buffered =================
#define G128_LDG()                                                                                 \
    a0 = *(const float4*)(Ap + k0);     a1 = *(const float4*)(Ap + k0 + 4);                        \
    b0 = *(const float4*)(Bp + k0);     b1 = *(const float4*)(Bp + k0 + 4);

#define G128_STORE(Ad, Bd)                                                                         \
    Ad[(lk + 0) * TP + lr] = a0.x; Ad[(lk + 1) * TP + lr] = a0.y;                                  \
    Ad[(lk + 2) * TP + lr] = a0.z; Ad[(lk + 3) * TP + lr] = a0.w;                                  \
    Ad[(lk + 4) * TP + lr] = a1.x; Ad[(lk + 5) * TP + lr] = a1.y;                                  \
    Ad[(lk + 6) * TP + lr] = a1.z; Ad[(lk + 7) * TP + lr] = a1.w;                                  \
    Bd[(lk + 0) * TP + lr] = b0.x; Bd[(lk + 1) * TP + lr] = b0.y;                                  \
    Bd[(lk + 2) * TP + lr] = b0.z; Bd[(lk + 3) * TP + lr] = b0.w;                                  \
    Bd[(lk + 4) * TP + lr] = b1.x; Bd[(lk + 5) * TP + lr] = b1.y;                                  \
    Bd[(lk + 6) * TP + lr] = b1.z; Bd[(lk + 7) * TP + lr] = b1.w;

#define G128_COMP(Ac, Bc)                                                                          \
    _Pragma("unroll")                                                                              \
    for (int kk = 0; kk < 16; ++kk) {                                                              \
        float4 av0 = *(const float4*)(Ac + kk * TP + ty * 8);                                      \
        float4 av1 = *(const float4*)(Ac + kk * TP + ty * 8 + 4);                                  \
        float4 bv0 = *(const float4*)(Bc + kk * TP + tx * 8);                                      \
        float4 bv1 = *(const float4*)(Bc + kk * TP + tx * 8 + 4);                                  \
        float ar[8] = {av0.x, av0.y, av0.z, av0.w, av1.x, av1.y, av1.z, av1.w};                    \
        float br[8] = {bv0.x, bv0.y, bv0.z, bv0.w, bv1.x, bv1.y, bv1.z, bv1.w};                    \
        _Pragma("unroll")                                                                          \
        for (int i = 0; i < 8; ++i)                                                                \
            _Pragma("unroll")                                                                      \
            for (int j = 0; j < 8; ++j) acc[i][j] += ar[i] * br[j];                                \
    }

// ---------------- C = A @ B^T + bias  (A: MxK rowmajor, B: NxK rowmajor) ----------------
__global__ __launch_bounds__(256, 2) void gemm128(const float* __restrict__ A,
                                                  const float* __restrict__ B,
                                                  const float* __restrict__ bias,
                                                  float* __restrict__ C,
                                                  int M, int N, int K)
{
    __shared__ float As[2][16 * TP];
    __shared__ float Bs[2][16 * TP];
    const int n0 = blockIdx.x * 128;
    const int m0 = blockIdx.y * 128;
    const int t  = threadIdx.x;
    const int tx = t & 15, ty = t >> 4;
    const int lr = t >> 1, lk = (t & 1) * 8;
    const float* Ap = A + (size_t)(m0 + lr) * K + lk;
    const float* Bp = B + (size_t)(n0 + lr) * K + lk;
    float acc[8][8] = {};
    float4 a0, a1, b0, b1;
    int k0 = 0;
    G128_LDG()
    { float* Ad = As[0]; float* Bd = Bs[0]; G128_STORE(Ad, Bd) }
    __syncthreads();
    int buf = 0;
    for (k0 = 16; k0 < K; k0 += 16) {
        G128_LDG()
        { const float* Ac = As[buf]; const float* Bc = Bs[buf]; G128_COMP(Ac, Bc) }
        { float* Ad = As[buf ^ 1]; float* Bd = Bs[buf ^ 1]; G128_STORE(Ad, Bd) }
        __syncthreads();
        buf ^= 1;
    }
    { const float* Ac = As[buf]; const float* Bc = Bs[buf]; G128_COMP(Ac, Bc) }

    float4 bb0 = *(const float4*)(bias + n0 + tx * 8);
    float4 bb1 = *(const float4*)(bias + n0 + tx * 8 + 4);
#pragma unroll
    for (int i = 0; i < 8; ++i) {
        float4 o0, o1;
        o0.x = acc[i][0] + bb0.x; o0.y = acc[i][1] + bb0.y;
        o0.z = acc[i][2] + bb0.z; o0.w = acc[i][3] + bb0.w;
        o1.x = acc[i][4] + bb1.x; o1.y = acc[i][5] + bb1.y;
        o1.z = acc[i][6] + bb1.z; o1.w = acc[i][7] + bb1.w;
        float* cp = C + (size_t)(m0 + ty * 8 + i) * N + n0 + tx * 8;
        *(float4*)cp       = o0;
        *(float4*)(cp + 4) = o1;
    }
}

// ---------------- per-slab dots = Qgr @ Kgr^T, fused square * scale ----------------
__global__ __launch_bounds__(256, 2) void dots128(const float* __restrict__ Qg,
                                                  const float* __restrict__ Kg,
                                                  float* __restrict__ G,
                                                  const float* __restrict__ scale_p)
{
    __shared__ float As[2][16 * TP];
    __shared__ float Bs[2][16 * TP];
    const int slab = blockIdx.z;
    const int m0 = blockIdx.x * 128;
    const int n0 = blockIdx.y * 128;
    const int t  = threadIdx.x;
    const int tx = t & 15, ty = t >> 4;
    const int lr = t >> 1, lk = (t & 1) * 8;
    const float* Ap = Qg + (size_t)slab * 256 * 64 + (size_t)(n0 + lr) * 64 + lk;
    const float* Bp = Kg + (size_t)slab * 256 * 64 + (size_t)(m0 + lr) * 64 + lk;
    float acc[8][8] = {};
    float4 a0, a1, b0, b1;
    int k0 = 0;
    G128_LDG()
    { float* Ad = As[0]; float* Bd = Bs[0]; G128_STORE(Ad, Bd) }
    __syncthreads();
    int buf = 0;
    for (k0 = 16; k0 < 64; k0 += 16) {
        G128_LDG()
        { const float* Ac = As[buf]; const float* Bc = Bs[buf]; G128_COMP(Ac, Bc) }
        { float* Ad = As[buf ^ 1]; float* Bd = Bs[buf ^ 1]; G128_STORE(Ad, Bd) }
        __syncthreads();
        buf ^= 1;
    }
    { const float* Ac = As[buf]; const float* Bc = Bs[buf]; G128_COMP(Ac, Bc) }

    const float sc = *scale_p;
#pragma unroll
    for (int i = 0; i < 8; ++i) {
        float4 o0, o1;
        o0.x = acc[i][0] * acc[i][0] * sc; o0.y = acc[i][1] * acc[i][1] * sc;
        o0.z = acc[i][2] * acc[i][2] * sc; o0.w = acc[i][3] * acc[i][3] * sc;
        o1.x = acc[i][4] * acc[i][4] * sc; o1.y = acc[i][5] * acc[i][5] * sc;
        o1.z = acc[i][6] * acc[i][6] * sc; o1.w = acc[i][7] * acc[i][7] * sc;
        float* gp = G + ((size_t)slab * 256 + n0 + ty * 8 + i) * 256 + m0 + tx * 8;
        *(float4*)gp       = o0;
        *(float4*)(gp + 4) = o1;
    }
}

// ---------------- per-slab Householder QR (LAPACK convention), Q via org2r ----------------
// 768 blocks: bid<384 -> q (coloff 0), else k (coloff 768). One 256-thread block per slab.
__global__ void qr_kernel(const float* __restrict__ Y, float* __restrict__ Qq,
                          float* __restrict__ Qk)
{
    extern __shared__ float A[];   // 64 * 257 floats
    __shared__ float tauv[64];
    __shared__ float red[8];
    __shared__ float s_tau, s_inv;
    const int bid = blockIdx.x;
    const int slab = (bid < 384) ? bid : bid - 384;
    const int coloff = (bid < 384) ? 0 : 768;
    float* Qout = (bid < 384) ? Qq : Qk;
    const int b = slab / 12, h = slab % 12;
    const float* src = Y + (size_t)b * 256 * 2304 + coloff + h * 64;
    const int t = threadIdx.x;
    const int lane = t & 31, wid = t >> 5;

    {   // load 256x64, store transposed (column-major)
        const int rloc = t >> 4, dg = (t & 15) << 2;
#pragma unroll
        for (int it = 0; it < 16; ++it) {
            int n = it * 16 + rloc;
            float4 v = *(const float4*)(src + (size_t)n * 2304 + dg);
            A[(dg + 0) * 257 + n] = v.x;
            A[(dg + 1) * 257 + n] = v.y;
            A[(dg + 2) * 257 + n] = v.z;
            A[(dg + 3) * 257 + n] = v.w;
        }
    }
    __syncthreads();

    // -------- geqf2 (unblocked Householder) --------
    for (int j = 0; j < 64; ++j) {
        float p = 0.f;
        if (t > j) { float x = A[j * 257 + t]; p = x * x; }
#pragma unroll
        for (int o = 16; o; o >>= 1) p += __shfl_xor_sync(0xffffffffu, p, o);
        if (lane == 0) red[wid] = p;
        __syncthreads();
        if (t == 0) {
            float xn2 = red[0] + red[1] + red[2] + red[3] + red[4] + red[5] + red[6] + red[7];
            float alpha = A[j * 257 + j];
            float tau, inv;
            if (xn2 <= 0.f) { tau = 0.f; inv = 0.f; }
            else {
                float nrm  = sqrtf(alpha * alpha + xn2);
                float beta = (alpha >= 0.f) ? -nrm : nrm;  // LAPACK dlarfg sign
                tau = (beta - alpha) / beta;
                inv = 1.f / (alpha - beta);
            }
            tauv[j] = tau; s_tau = tau; s_inv = inv;
        }
        __syncthreads();
        float tau = s_tau;
        if (t > j) A[j * 257 + t] *= s_inv;   // v (v0=1 implicit)
        __syncthreads();
        float vr[8];
#pragma unroll
        for (int r = 0; r < 8; ++r) {
            int i = j + lane + 32 * r;
            vr[r] = (i < 256) ? ((i == j) ? 1.f : A[j * 257 + i]) : 0.f;
        }
        for (int k = j + 1 + wid; k < 64; k += 8) {
            float s = 0.f, ar[8];
#pragma unroll
            for (int r = 0; r < 8; ++r) {
                int i = j + lane + 32 * r;
                ar[r] = (i < 256) ? A[k * 257 + i] : 0.f;
                s += vr[r] * ar[r];
            }
#pragma unroll
            for (int o = 16; o; o >>= 1) s += __shfl_xor_sync(0xffffffffu, s, o);
            float ts = tau * s;
#pragma unroll
            for (int r = 0; r < 8; ++r) {
                int i = j + lane + 32 * r;
                if (i < 256) A[k * 257 + i] = ar[r] - ts * vr[r];
            }
        }
        __syncthreads();
    }

    // -------- org2r: form Q in place (backward accumulation) --------
    for (int j = 63; j >= 0; --j) {
        float tau = tauv[j];
        float vr[8];
#pragma unroll
        for (int r = 0; r < 8; ++r) {
            int i = j + lane + 32 * r;
            vr[r] = (i < 256) ? ((i == j) ? 1.f : A[j * 257 + i]) : 0.f;
        }
        for (int k = j + 1 + wid; k < 64; k += 8) {
            float s = 0.f, ar[8];
#pragma unroll
            for (int r = 0; r < 8; ++r) {
                int i = j + lane + 32 * r;
                ar[r] = (i < 256) ? A[k * 257 + i] : 0.f;
                s += vr[r] * ar[r];
            }
#pragma unroll
            for (int o = 16; o; o >>= 1) s += __shfl_xor_sync(0xffffffffu, s, o);
            float ts = tau * s;
#pragma unroll
            for (int r = 0; r < 8; ++r) {
                int i = j + lane + 32 * r;
                if (i < 256) A[k * 257 + i] = ar[r] - ts * vr[r];
            }
        }
        __syncthreads();
        {
            float val;
            if (t < j)       val = 0.f;
            else if (t == j) val = 1.f - tau;
            else             val = -tau * A[j * 257 + t];
            A[j * 257 + t] = val;
        }
        __syncthreads();
    }

    {   // store Q packed [slab][n][d]
        const int rloc = t >> 4, dg = (t & 15) << 2;
#pragma unroll
        for (int it = 0; it < 16; ++it) {
            int n = it * 16 + rloc;
            float4 v;
            v.x = A[(dg + 0) * 257 + n];
            v.y = A[(dg + 1) * 257 + n];
            v.z = A[(dg + 2) * 257 + n];
            v.w = A[(dg + 3) * 257 + n];
            *(float4*)(Qout + ((size_t)slab * 256 + n) * 64 + dg) = v;
        }
    }
}

// ---------------- cross-head 1x1-conv mix + softmax, in place on G ----------------
__global__ void mix_softmax(float* __restrict__ G, const float* __restrict__ cw,
                            const float* __restrict__ cbg)
{
    __shared__ float gsm[12 * 256];
    __shared__ float w2[144];
    __shared__ float cb[12];
    const int n = blockIdx.x, b = blockIdx.y;
    const int t = threadIdx.x;          // 384
    const int lane = t & 31, wo = t >> 5;
    if (t < 144) { int o = t / 12, h = t % 12; w2[t] = cw[o * 24 + h] + cw[o * 24 + 12 + h]; }
    if (t < 12) cb[t] = cbg[t];
    {
        float* dstp = gsm + wo * 256;
        const float* srcp = G + ((size_t)(b * 12 + wo) * 256 + n) * 256;
        *(float4*)(dstp + lane * 4)       = *(const float4*)(srcp + lane * 4);
        *(float4*)(dstp + 128 + lane * 4) = *(const float4*)(srcp + 128 + lane * 4);
    }
    __syncthreads();
    float vals[8];
    float mx = -3.4e38f;
#pragma unroll
    for (int r = 0; r < 8; ++r) {
        int m = lane + 32 * r;
        float s = cb[wo];
#pragma unroll
        for (int h = 0; h < 12; ++h) s += w2[wo * 12 + h] * gsm[h * 256 + m];
        vals[r] = s;
        mx = fmaxf(mx, s);
    }
#pragma unroll
    for (int o = 16; o; o >>= 1) mx = fmaxf(mx, __shfl_xor_sync(0xffffffffu, mx, o));
    float sum = 0.f;
#pragma unroll
    for (int r = 0; r < 8; ++r) { vals[r] = expf(vals[r] - mx); sum += vals[r]; }
#pragma unroll
    for (int o = 16; o; o >>= 1) sum += __shfl_xor_sync(0xffffffffu, sum, o);
    float inv = 1.f / sum;
    float* dst = G + ((size_t)(b * 12 + wo) * 256 + n) * 256;
#pragma unroll
    for (int r = 0; r < 8; ++r) dst[lane + 32 * r] = vals[r] * inv;
}

// ---------------- out_h = attn @ v  (128x64 tile, 8x4/thread, double-buffered) ----------------
__global__ __launch_bounds__(256, 2) void attnv128(const float* __restrict__ Attn,
                                                   const float* __restrict__ Y,
                                                   float* __restrict__ AO)
{
    __shared__ float As[2][16 * TP];  // [kk][n-row], transposed attn tile
    __shared__ float Bs[2][16 * VP];  // [kk][d]
    const int slab = blockIdx.y;
    const int b = slab / 12, h = slab % 12;
    const int n0 = blockIdx.x * 128;
    const float* Ap = Attn + (size_t)slab * 256 * 256;
    const float* Vp = Y + (size_t)b * 256 * 2304 + 1536 + h * 64;
    const int t = threadIdx.x;
    const int tx = t & 15, ty = t >> 4;
    const int ar = t >> 2, ag = (t & 3) << 2;   // attn: rows ar, ar+64; cols ag..ag+3
    const int vr = t >> 4, vg = (t & 15) << 2;  // V: row vr; cols vg..vg+3
    float acc[8][4] = {};
    float4 a0, a1, v0;
    int m0 = 0;
    a0 = *(const float4*)(Ap + (size_t)(n0 + ar) * 256 + m0 + ag);
    a1 = *(const float4*)(Ap + (size_t)(n0 + 64 + ar) * 256 + m0 + ag);
    v0 = *(const float4*)(Vp + (size_t)(m0 + vr) * 2304 + vg);
    {
        float* Ad = As[0]; float* Bd = Bs[0];
        Ad[(ag + 0) * TP + ar] = a0.x; Ad[(ag + 1) * TP + ar] = a0.y;
        Ad[(ag + 2) * TP + ar] = a0.z; Ad[(ag + 3) * TP + ar] = a0.w;
        Ad[(ag + 0) * TP + 64 + ar] = a1.x; Ad[(ag + 1) * TP + 64 + ar] = a1.y;
        Ad[(ag + 2) * TP + 64 + ar] = a1.z; Ad[(ag + 3) * TP + 64 + ar] = a1.w;
        *(float4*)(Bd + vr * VP + vg) = v0;
    }
    __syncthreads();
    int buf = 0;
    for (m0 = 16; m0 < 256; m0 += 16) {
        a0 = *(const float4*)(Ap + (size_t)(n0 + ar) * 256 + m0 + ag);
        a1 = *(const float4*)(Ap + (size_t)(n0 + 64 + ar) * 256 + m0 + ag);
        v0 = *(const float4*)(Vp + (size_t)(m0 + vr) * 2304 + vg);
        {
            const float* Ac = As[buf]; const float* Bc = Bs[buf];
#pragma unroll
            for (int kk = 0; kk < 16; ++kk) {
                float4 av0 = *(const float4*)(Ac + kk * TP + ty * 8);
                float4 av1 = *(const float4*)(Ac + kk * TP + ty * 8 + 4);
                float4 bv  = *(const float4*)(Bc + kk * VP + tx * 4);
                float arr[8] = {av0.x, av0.y, av0.z, av0.w, av1.x, av1.y, av1.z, av1.w};
#pragma unroll
                for (int i = 0; i < 8; ++i) {
                    acc[i][0] += arr[i] * bv.x; acc[i][1] += arr[i] * bv.y;
                    acc[i][2] += arr[i] * bv.z; acc[i][3] += arr[i] * bv.w;
                }
            }
        }
        {
            float* Ad = As[buf ^ 1]; float* Bd = Bs[buf ^ 1];
            Ad[(ag + 0) * TP + ar] = a0.x; Ad[(ag + 1) * TP + ar] = a0.y;
            Ad[(ag + 2) * TP + ar] = a0.z; Ad[(ag + 3) * TP + ar] = a0.w;
            Ad[(ag + 0) * TP + 64 + ar] = a1.x; Ad[(ag + 1) * TP + 64 + ar] = a1.y;
            Ad[(ag + 2) * TP + 64 + ar] = a1.z; Ad[(ag + 3) * TP + 64 + ar] = a1.w;
            *(float4*)(Bd + vr * VP + vg) = v0;
        }
        __syncthreads();
        buf ^= 1;
    }
    {
        const float* Ac = As[buf]; const float* Bc = Bs[buf];
#pragma unroll
        for (int kk = 0; kk < 16; ++kk) {
            float4 av0 = *(const float4*)(Ac + kk * TP + ty * 8);
            float4 av1 = *(const float4*)(Ac + kk * TP + ty * 8 + 4);
            float4 bv  = *(const float4*)(Bc + kk * VP + tx * 4);
            float arr[8] = {av0.x, av0.y, av0.z, av0.w, av1.x, av1.y, av1.z, av1.w};
#pragma unroll
            for (int i = 0; i < 8; ++i) {
                acc[i][0] += arr[i] * bv.x; acc[i][1] += arr[i] * bv.y;
                acc[i][2] += arr[i] * bv.z; acc[i][3] += arr[i] * bv.w;
            }
        }
    }
#pragma unroll
    for (int i = 0; i < 8; ++i) {
        float4 o;
        o.x = acc[i][0]; o.y = acc[i][1]; o.z = acc[i][2]; o.w = acc[i][3];
        *(float4*)(AO + (size_t)(b * 256 + n0 + ty * 8 + i) * 768 + h * 64 + tx * 4) = o;
    }
}

// ---------------- launch ----------------
extern "C" void kernel_launch(void* const* d_in, const int* in_sizes, int n_in,
                              void* d_out, int out_size)
{
    (void)in_sizes; (void)n_in; (void)out_size;
    const float* x    = (const float*)d_in[0];
    const float* qkvw = (const float*)d_in[1];
    const float* qkvb = (const float*)d_in[2];
    const float* gsc  = (const float*)d_in[3];
    const float* cw   = (const float*)d_in[4];
    const float* cb   = (const float*)d_in[5];
    const float* pw   = (const float*)d_in[6];
    const float* pb   = (const float*)d_in[7];
    float* out = (float*)d_out;

    float *Y, *qgr, *kgr, *attn, *ao;
    cudaGetSymbolAddress((void**)&Y, g_Y);
    cudaGetSymbolAddress((void**)&qgr, g_qgr);
    cudaGetSymbolAddress((void**)&kgr, g_kgr);
    cudaGetSymbolAddress((void**)&attn, g_attn);
    cudaGetSymbolAddress((void**)&ao, g_ao);

    cudaFuncSetAttribute(qr_kernel, cudaFuncAttributeMaxDynamicSharedMemorySize, 64 * 257 * 4);

    // 1) QKV: Y = x @ qkv_w^T + qkv_b      (8192 x 2304, K=768)
    gemm128<<<dim3(2304 / 128, 8192 / 128), 256>>>(x, qkvw, qkvb, Y, 8192, 2304, 768);
    // 2) Householder QR per (b,h) slab for q AND k in one launch (768 blocks)
    qr_kernel<<<768, 256, 64 * 257 * 4>>>(Y, qgr, kgr);
    // 3) dots^2 * scale per slab (128x128 tiles)
    dots128<<<dim3(2, 2, 384), 256>>>(qgr, kgr, attn, gsc);
    // 4) cross-head mix + softmax (in place)
    mix_softmax<<<dim3(256, 32), 384>>>(attn, cw, cb);
    // 5) attn @ v  -> (b,n,h*64+d)
    attnv128<<<dim3(2, 384), 256>>>(attn, Y, ao);
    // 6) proj: out = ao @ proj_w^T + proj_b
    gemm128<<<dim3(768 / 128, 8192 / 128), 256>>>(ao, pw, pb, out, 8192, 768, 768);
}

// round 8
// speedup vs baseline: 1.2876x; 1.1214x over previous
#include <cuda_runtime.h>
#include <cstdint>

#define TP 132     // 128-wide tile pitch (words)
#define VP 68      // 64-wide tile pitch (words)

typedef unsigned long long u64t;

// ---------------- packed f32x2 helpers (FFMA2 path, sm_103a) ----------------
__device__ __forceinline__ u64t pk2(float x, float y) {
    u64t r; asm("mov.b64 %0, {%1,%2};" : "=l"(r) : "f"(x), "f"(y)); return r;
}
__device__ __forceinline__ u64t ffma2(u64t a, u64t b, u64t c) {
    u64t d; asm("fma.rn.f32x2 %0, %1, %2, %3;" : "=l"(d) : "l"(a), "l"(b), "l"(c)); return d;
}
__device__ __forceinline__ u64t add2(u64t a, u64t b) {
    u64t d; asm("add.rn.f32x2 %0, %1, %2;" : "=l"(d) : "l"(a), "l"(b)); return d;
}
__device__ __forceinline__ u64t mul2(u64t a, u64t b) {
    u64t d; asm("mul.rn.f32x2 %0, %1, %2;" : "=l"(d) : "l"(a), "l"(b)); return d;
}

// ---------------- scratch (device globals; no allocation allowed) ----------------
__device__ float g_Y[8192ULL * 2304];      // QKV output (B*N, 3*H*d): t*768 + h*64 + d
__device__ float g_qgr[384ULL * 256 * 64]; // Q-grassmann  [slab][n][d], slab = b*12+h
__device__ float g_kgr[384ULL * 256 * 64];
__device__ float g_attn[384ULL * 256 * 256]; // dots^2*scale, then (in-place) softmaxed attn
__device__ float g_ao[8192ULL * 768];      // attn@V, (b,n,h,d) flattened

// ================= 128x128x16 GEMM core: 8x8 per thread, packed f32x2, double-buffered ========
// Thread tile: rows ty*8..+7 ; cols {tx*4..+3} U {64+tx*4..+3}  (conflict-free B LDS)
#define G128_LDG()                                                                                 \
    a0 = *(const float4*)(Ap + k0);     a1 = *(const float4*)(Ap + k0 + 4);                        \
    b0 = *(const float4*)(Bp + k0);     b1 = *(const float4*)(Bp + k0 + 4);

#define G128_STORE(Ad, Bd)                                                                         \
    Ad[(lk + 0) * TP + lr] = a0.x; Ad[(lk + 1) * TP + lr] = a0.y;                                  \
    Ad[(lk + 2) * TP + lr] = a0.z; Ad[(lk + 3) * TP + lr] = a0.w;                                  \
    Ad[(lk + 4) * TP + lr] = a1.x; Ad[(lk + 5) * TP + lr] = a1.y;                                  \
    Ad[(lk + 6) * TP + lr] = a1.z; Ad[(lk + 7) * TP + lr] = a1.w;                                  \
    Bd[(lk + 0) * TP + lr] = b0.x; Bd[(lk + 1) * TP + lr] = b0.y;                                  \
    Bd[(lk + 2) * TP + lr] = b0.z; Bd[(lk + 3) * TP + lr] = b0.w;                                  \
    Bd[(lk + 4) * TP + lr] = b1.x; Bd[(lk + 5) * TP + lr] = b1.y;                                  \
    Bd[(lk + 6) * TP + lr] = b1.z; Bd[(lk + 7) * TP + lr] = b1.w;

#define G128_COMP(Ac, Bc)                                                                          \
    _Pragma("unroll")                                                                              \
    for (int kk = 0; kk < 16; ++kk) {                                                              \
        float4 av0 = *(const float4*)(Ac + kk * TP + ty * 8);                                      \
        float4 av1 = *(const float4*)(Ac + kk * TP + ty * 8 + 4);                                  \
        ulonglong2 bL = *(const ulonglong2*)(Bc + kk * TP + tx * 4);                               \
        ulonglong2 bR = *(const ulonglong2*)(Bc + kk * TP + 64 + tx * 4);                          \
        float ar[8] = {av0.x, av0.y, av0.z, av0.w, av1.x, av1.y, av1.z, av1.w};                    \
        _Pragma("unroll")                                                                          \
        for (int i = 0; i < 8; ++i) {                                                              \
            u64t aa = pk2(ar[i], ar[i]);                                                           \
            acc2[i][0] = ffma2(aa, bL.x, acc2[i][0]);                                              \
            acc2[i][1] = ffma2(aa, bL.y, acc2[i][1]);                                              \
            acc2[i][2] = ffma2(aa, bR.x, acc2[i][2]);                                              \
            acc2[i][3] = ffma2(aa, bR.y, acc2[i][3]);                                              \
        }                                                                                          \
    }

// ---------------- C = A @ B^T + bias  (A: MxK rowmajor, B: NxK rowmajor) ----------------
__global__ __launch_bounds__(256, 2) void gemm128(const float* __restrict__ A,
                                                  const float* __restrict__ B,
                                                  const float* __restrict__ bias,
                                                  float* __restrict__ C,
                                                  int M, int N, int K)
{
    __shared__ float As[2][16 * TP];
    __shared__ float Bs[2][16 * TP];
    const int n0 = blockIdx.x * 128;
    const int m0 = blockIdx.y * 128;
    const int t  = threadIdx.x;
    const int tx = t & 15, ty = t >> 4;
    const int lr = t >> 1, lk = (t & 1) * 8;
    const float* Ap = A + (size_t)(m0 + lr) * K + lk;
    const float* Bp = B + (size_t)(n0 + lr) * K + lk;
    u64t acc2[8][4] = {};
    float4 a0, a1, b0, b1;
    int k0 = 0;
    G128_LDG()
    { float* Ad = As[0]; float* Bd = Bs[0]; G128_STORE(Ad, Bd) }
    __syncthreads();
    int buf = 0;
    for (k0 = 16; k0 < K; k0 += 16) {
        G128_LDG()
        { const float* Ac = As[buf]; const float* Bc = Bs[buf]; G128_COMP(Ac, Bc) }
        { float* Ad = As[buf ^ 1]; float* Bd = Bs[buf ^ 1]; G128_STORE(Ad, Bd) }
        __syncthreads();
        buf ^= 1;
    }
    { const float* Ac = As[buf]; const float* Bc = Bs[buf]; G128_COMP(Ac, Bc) }

    float4 bbl = *(const float4*)(bias + n0 + tx * 4);
    float4 bbr = *(const float4*)(bias + n0 + 64 + tx * 4);
    u64t bL0 = pk2(bbl.x, bbl.y), bL1 = pk2(bbl.z, bbl.w);
    u64t bR0 = pk2(bbr.x, bbr.y), bR1 = pk2(bbr.z, bbr.w);
#pragma unroll
    for (int i = 0; i < 8; ++i) {
        float* cp = C + (size_t)(m0 + ty * 8 + i) * N + n0 + tx * 4;
        ulonglong2 s0, s1;
        s0.x = add2(acc2[i][0], bL0); s0.y = add2(acc2[i][1], bL1);
        s1.x = add2(acc2[i][2], bR0); s1.y = add2(acc2[i][3], bR1);
        *(ulonglong2*)cp        = s0;
        *(ulonglong2*)(cp + 64) = s1;
    }
}

// ---------------- per-slab dots = Qgr @ Kgr^T, fused square * scale ----------------
__global__ __launch_bounds__(256, 2) void dots128(const float* __restrict__ Qg,
                                                  const float* __restrict__ Kg,
                                                  float* __restrict__ G,
                                                  const float* __restrict__ scale_p)
{
    __shared__ float As[2][16 * TP];
    __shared__ float Bs[2][16 * TP];
    const int slab = blockIdx.z;
    const int m0 = blockIdx.x * 128;
    const int n0 = blockIdx.y * 128;
    const int t  = threadIdx.x;
    const int tx = t & 15, ty = t >> 4;
    const int lr = t >> 1, lk = (t & 1) * 8;
    const float* Ap = Qg + (size_t)slab * 256 * 64 + (size_t)(n0 + lr) * 64 + lk;
    const float* Bp = Kg + (size_t)slab * 256 * 64 + (size_t)(m0 + lr) * 64 + lk;
    u64t acc2[8][4] = {};
    float4 a0, a1, b0, b1;
    int k0 = 0;
    G128_LDG()
    { float* Ad = As[0]; float* Bd = Bs[0]; G128_STORE(Ad, Bd) }
    __syncthreads();
    int buf = 0;
    for (k0 = 16; k0 < 64; k0 += 16) {
        G128_LDG()
        { const float* Ac = As[buf]; const float* Bc = Bs[buf]; G128_COMP(Ac, Bc) }
        { float* Ad = As[buf ^ 1]; float* Bd = Bs[buf ^ 1]; G128_STORE(Ad, Bd) }
        __syncthreads();
        buf ^= 1;
    }
    { const float* Ac = As[buf]; const float* Bc = Bs[buf]; G128_COMP(Ac, Bc) }

    const float sc = *scale_p;
    const u64t scp = pk2(sc, sc);
#pragma unroll
    for (int i = 0; i < 8; ++i) {
        float* gp = G + ((size_t)slab * 256 + n0 + ty * 8 + i) * 256 + m0 + tx * 4;
        ulonglong2 s0, s1;
        s0.x = mul2(mul2(acc2[i][0], acc2[i][0]), scp);
        s0.y = mul2(mul2(acc2[i][1], acc2[i][1]), scp);
        s1.x = mul2(mul2(acc2[i][2], acc2[i][2]), scp);
        s1.y = mul2(mul2(acc2[i][3], acc2[i][3]), scp);
        *(ulonglong2*)gp        = s0;
        *(ulonglong2*)(gp + 64) = s1;
    }
}

// ---------------- per-slab Householder QR (LAPACK convention), Q via org2r ----------------
// 768 blocks: bid<384 -> q (coloff 0), else k (coloff 768). One 256-thread block per slab.
__global__ void qr_kernel(const float* __restrict__ Y, float* __restrict__ Qq,
                          float* __restrict__ Qk)
{
    extern __shared__ float A[];   // 64 * 257 floats
    __shared__ float tauv[64];
    __shared__ float red[8];
    __shared__ float s_tau, s_inv;
    const int bid = blockIdx.x;
    const int slab = (bid < 384) ? bid : bid - 384;
    const int coloff = (bid < 384) ? 0 : 768;
    float* Qout = (bid < 384) ? Qq : Qk;
    const int b = slab / 12, h = slab % 12;
    const float* src = Y + (size_t)b * 256 * 2304 + coloff + h * 64;
    const int t = threadIdx.x;
    const int lane = t & 31, wid = t >> 5;

    {   // load 256x64, store transposed (column-major)
        const int rloc = t >> 4, dg = (t & 15) << 2;
#pragma unroll
        for (int it = 0; it < 16; ++it) {
            int n = it * 16 + rloc;
            float4 v = *(const float4*)(src + (size_t)n * 2304 + dg);
            A[(dg + 0) * 257 + n] = v.x;
            A[(dg + 1) * 257 + n] = v.y;
            A[(dg + 2) * 257 + n] = v.z;
            A[(dg + 3) * 257 + n] = v.w;
        }
    }
    __syncthreads();

    // -------- geqf2 (unblocked Householder) --------
    for (int j = 0; j < 64; ++j) {
        float p = 0.f;
        if (t > j) { float x = A[j * 257 + t]; p = x * x; }
#pragma unroll
        for (int o = 16; o; o >>= 1) p += __shfl_xor_sync(0xffffffffu, p, o);
        if (lane == 0) red[wid] = p;
        __syncthreads();
        if (t == 0) {
            float xn2 = red[0] + red[1] + red[2] + red[3] + red[4] + red[5] + red[6] + red[7];
            float alpha = A[j * 257 + j];
            float tau, inv;
            if (xn2 <= 0.f) { tau = 0.f; inv = 0.f; }
            else {
                float nrm  = sqrtf(alpha * alpha + xn2);
                float beta = (alpha >= 0.f) ? -nrm : nrm;  // LAPACK dlarfg sign
                tau = (beta - alpha) / beta;
                inv = 1.f / (alpha - beta);
            }
            tauv[j] = tau; s_tau = tau; s_inv = inv;
        }
        __syncthreads();
        float tau = s_tau;
        if (t > j) A[j * 257 + t] *= s_inv;   // v (v0=1 implicit)
        __syncthreads();
        float vr[8];
#pragma unroll
        for (int r = 0; r < 8; ++r) {
            int i = j + lane + 32 * r;
            vr[r] = (i < 256) ? ((i == j) ? 1.f : A[j * 257 + i]) : 0.f;
        }
        for (int k = j + 1 + wid; k < 64; k += 8) {
            float s = 0.f, ar[8];
#pragma unroll
            for (int r = 0; r < 8; ++r) {
                int i = j + lane + 32 * r;
                ar[r] = (i < 256) ? A[k * 257 + i] : 0.f;
                s += vr[r] * ar[r];
            }
#pragma unroll
            for (int o = 16; o; o >>= 1) s += __shfl_xor_sync(0xffffffffu, s, o);
            float ts = tau * s;
#pragma unroll
            for (int r = 0; r < 8; ++r) {
                int i = j + lane + 32 * r;
                if (i < 256) A[k * 257 + i] = ar[r] - ts * vr[r];
            }
        }
        __syncthreads();
    }

    // -------- org2r: form Q in place (backward accumulation) --------
    for (int j = 63; j >= 0; --j) {
        float tau = tauv[j];
        float vr[8];
#pragma unroll
        for (int r = 0; r < 8; ++r) {
            int i = j + lane + 32 * r;
            vr[r] = (i < 256) ? ((i == j) ? 1.f : A[j * 257 + i]) : 0.f;
        }
        for (int k = j + 1 + wid; k < 64; k += 8) {
            float s = 0.f, ar[8];
#pragma unroll
            for (int r = 0; r < 8; ++r) {
                int i = j + lane + 32 * r;
                ar[r] = (i < 256) ? A[k * 257 + i] : 0.f;
                s += vr[r] * ar[r];
            }
#pragma unroll
            for (int o = 16; o; o >>= 1) s += __shfl_xor_sync(0xffffffffu, s, o);
            float ts = tau * s;
#pragma unroll
            for (int r = 0; r < 8; ++r) {
                int i = j + lane + 32 * r;
                if (i < 256) A[k * 257 + i] = ar[r] - ts * vr[r];
            }
        }
        __syncthreads();
        {
            float val;
            if (t < j)       val = 0.f;
            else if (t == j) val = 1.f - tau;
            else             val = -tau * A[j * 257 + t];
            A[j * 257 + t] = val;
        }
        __syncthreads();
    }

    {   // store Q packed [slab][n][d]
        const int rloc = t >> 4, dg = (t & 15) << 2;
#pragma unroll
        for (int it = 0; it < 16; ++it) {
            int n = it * 16 + rloc;
            float4 v;
            v.x = A[(dg + 0) * 257 + n];
            v.y = A[(dg + 1) * 257 + n];
            v.z = A[(dg + 2) * 257 + n];
            v.w = A[(dg + 3) * 257 + n];
            *(float4*)(Qout + ((size_t)slab * 256 + n) * 64 + dg) = v;
        }
    }
}

// ---------------- cross-head 1x1-conv mix + softmax, in place on G ----------------
__global__ void mix_softmax(float* __restrict__ G, const float* __restrict__ cw,
                            const float* __restrict__ cbg)
{
    __shared__ float gsm[12 * 256];
    __shared__ float w2[144];
    __shared__ float cb[12];
    const int n = blockIdx.x, b = blockIdx.y;
    const int t = threadIdx.x;          // 384
    const int lane = t & 31, wo = t >> 5;
    if (t < 144) { int o = t / 12, h = t % 12; w2[t] = cw[o * 24 + h] + cw[o * 24 + 12 + h]; }
    if (t < 12) cb[t] = cbg[t];
    {
        float* dstp = gsm + wo * 256;
        const float* srcp = G + ((size_t)(b * 12 + wo) * 256 + n) * 256;
        *(float4*)(dstp + lane * 4)       = *(const float4*)(srcp + lane * 4);
        *(float4*)(dstp + 128 + lane * 4) = *(const float4*)(srcp + 128 + lane * 4);
    }
    __syncthreads();
    float vals[8];
    float mx = -3.4e38f;
#pragma unroll
    for (int r = 0; r < 8; ++r) {
        int m = lane + 32 * r;
        float s = cb[wo];
#pragma unroll
        for (int h = 0; h < 12; ++h) s += w2[wo * 12 + h] * gsm[h * 256 + m];
        vals[r] = s;
        mx = fmaxf(mx, s);
    }
#pragma unroll
    for (int o = 16; o; o >>= 1) mx = fmaxf(mx, __shfl_xor_sync(0xffffffffu, mx, o));
    float sum = 0.f;
#pragma unroll
    for (int r = 0; r < 8; ++r) { vals[r] = expf(vals[r] - mx); sum += vals[r]; }
#pragma unroll
    for (int o = 16; o; o >>= 1) sum += __shfl_xor_sync(0xffffffffu, sum, o);
    float inv = 1.f / sum;
    float* dst = G + ((size_t)(b * 12 + wo) * 256 + n) * 256;
#pragma unroll
    for (int r = 0; r < 8; ++r) dst[lane + 32 * r] = vals[r] * inv;
}

// ---------------- out_h = attn @ v  (128x64 tile, 8x4/thread packed, double-buffered) ---------
__global__ __launch_bounds__(256, 2) void attnv128(const float* __restrict__ Attn,
                                                   const float* __restrict__ Y,
                                                   float* __restrict__ AO)
{
    __shared__ float As[2][16 * TP];  // [kk][n-row], transposed attn tile
    __shared__ float Bs[2][16 * VP];  // [kk][d]
    const int slab = blockIdx.y;
    const int b = slab / 12, h = slab % 12;
    const int n0 = blockIdx.x * 128;
    const float* Ap = Attn + (size_t)slab * 256 * 256;
    const float* Vp = Y + (size_t)b * 256 * 2304 + 1536 + h * 64;
    const int t = threadIdx.x;
    const int tx = t & 15, ty = t >> 4;
    const int ar = t >> 2, ag = (t & 3) << 2;   // attn: rows ar, ar+64; cols ag..ag+3
    const int vr = t >> 4, vg = (t & 15) << 2;  // V: row vr; cols vg..vg+3
    u64t acc2[8][2] = {};
    float4 a0, a1, v0;
    int m0 = 0;
    a0 = *(const float4*)(Ap + (size_t)(n0 + ar) * 256 + m0 + ag);
    a1 = *(const float4*)(Ap + (size_t)(n0 + 64 + ar) * 256 + m0 + ag);
    v0 = *(const float4*)(Vp + (size_t)(m0 + vr) * 2304 + vg);
    {
        float* Ad = As[0]; float* Bd = Bs[0];
        Ad[(ag + 0) * TP + ar] = a0.x; Ad[(ag + 1) * TP + ar] = a0.y;
        Ad[(ag + 2) * TP + ar] = a0.z; Ad[(ag + 3) * TP + ar] = a0.w;
        Ad[(ag + 0) * TP + 64 + ar] = a1.x; Ad[(ag + 1) * TP + 64 + ar] = a1.y;
        Ad[(ag + 2) * TP + 64 + ar] = a1.z; Ad[(ag + 3) * TP + 64 + ar] = a1.w;
        *(float4*)(Bd + vr * VP + vg) = v0;
    }
    __syncthreads();
    int buf = 0;
    for (m0 = 16; m0 < 256; m0 += 16) {
        a0 = *(const float4*)(Ap + (size_t)(n0 + ar) * 256 + m0 + ag);
        a1 = *(const float4*)(Ap + (size_t)(n0 + 64 + ar) * 256 + m0 + ag);
        v0 = *(const float4*)(Vp + (size_t)(m0 + vr) * 2304 + vg);
        {
            const float* Ac = As[buf]; const float* Bc = Bs[buf];
#pragma unroll
            for (int kk = 0; kk < 16; ++kk) {
                float4 av0 = *(const float4*)(Ac + kk * TP + ty * 8);
                float4 av1 = *(const float4*)(Ac + kk * TP + ty * 8 + 4);
                ulonglong2 bb = *(const ulonglong2*)(Bc + kk * VP + tx * 4);
                float arr[8] = {av0.x, av0.y, av0.z, av0.w, av1.x, av1.y, av1.z, av1.w};
#pragma unroll
                for (int i = 0; i < 8; ++i) {
                    u64t aa = pk2(arr[i], arr[i]);
                    acc2[i][0] = ffma2(aa, bb.x, acc2[i][0]);
                    acc2[i][1] = ffma2(aa, bb.y, acc2[i][1]);
                }
            }
        }
        {
            float* Ad = As[buf ^ 1]; float* Bd = Bs[buf ^ 1];
            Ad[(ag + 0) * TP + ar] = a0.x; Ad[(ag + 1) * TP + ar] = a0.y;
            Ad[(ag + 2) * TP + ar] = a0.z; Ad[(ag + 3) * TP + ar] = a0.w;
            Ad[(ag + 0) * TP + 64 + ar] = a1.x; Ad[(ag + 1) * TP + 64 + ar] = a1.y;
            Ad[(ag + 2) * TP + 64 + ar] = a1.z; Ad[(ag + 3) * TP + 64 + ar] = a1.w;
            *(float4*)(Bd + vr * VP + vg) = v0;
        }
        __syncthreads();
        buf ^= 1;
    }
    {
        const float* Ac = As[buf]; const float* Bc = Bs[buf];
#pragma unroll
        for (int kk = 0; kk < 16; ++kk) {
            float4 av0 = *(const float4*)(Ac + kk * TP + ty * 8);
            float4 av1 = *(const float4*)(Ac + kk * TP + ty * 8 + 4);
            ulonglong2 bb = *(const ulonglong2*)(Bc + kk * VP + tx * 4);
            float arr[8] = {av0.x, av0.y, av0.z, av0.w, av1.x, av1.y, av1.z, av1.w};
#pragma unroll
            for (int i = 0; i < 8; ++i) {
                u64t aa = pk2(arr[i], arr[i]);
                acc2[i][0] = ffma2(aa, bb.x, acc2[i][0]);
                acc2[i][1] = ffma2(aa, bb.y, acc2[i][1]);
            }
        }
    }
#pragma unroll
    for (int i = 0; i < 8; ++i) {
        ulonglong2 s;
        s.x = acc2[i][0]; s.y = acc2[i][1];
        *(ulonglong2*)(AO + (size_t)(b * 256 + n0 + ty * 8 + i) * 768 + h * 64 + tx * 4) = s;
    }
}

// ---------------- launch ----------------
extern "C" void kernel_launch(void* const* d_in, const int* in_sizes, int n_in,
                              void* d_out, int out_size)
{
    (void)in_sizes; (void)n_in; (void)out_size;
    const float* x    = (const float*)d_in[0];
    const float* qkvw = (const float*)d_in[1];
    const float* qkvb = (const float*)d_in[2];
    const float* gsc  = (const float*)d_in[3];
    const float* cw   = (const float*)d_in[4];
    const float* cb   = (const float*)d_in[5];
    const float* pw   = (const float*)d_in[6];
    const float* pb   = (const float*)d_in[7];
    float* out = (float*)d_out;

    float *Y, *qgr, *kgr, *attn, *ao;
    cudaGetSymbolAddress((void**)&Y, g_Y);
    cudaGetSymbolAddress((void**)&qgr, g_qgr);
    cudaGetSymbolAddress((void**)&kgr, g_kgr);
    cudaGetSymbolAddress((void**)&attn, g_attn);
    cudaGetSymbolAddress((void**)&ao, g_ao);

    cudaFuncSetAttribute(qr_kernel, cudaFuncAttributeMaxDynamicSharedMemorySize, 64 * 257 * 4);

    // 1) QKV: Y = x @ qkv_w^T + qkv_b      (8192 x 2304, K=768)
    gemm128<<<dim3(2304 / 128, 8192 / 128), 256>>>(x, qkvw, qkvb, Y, 8192, 2304, 768);
    // 2) Householder QR per (b,h) slab for q AND k in one launch (768 blocks)
    qr_kernel<<<768, 256, 64 * 257 * 4>>>(Y, qgr, kgr);
    // 3) dots^2 * scale per slab (128x128 tiles)
    dots128<<<dim3(2, 2, 384), 256>>>(qgr, kgr, attn, gsc);
    // 4) cross-head mix + softmax (in place)
    mix_softmax<<<dim3(256, 32), 384>>>(attn, cw, cb);
    // 5) attn @ v  -> (b,n,h*64+d)
    attnv128<<<dim3(2, 384), 256>>>(attn, Y, ao);
    // 6) proj: out = ao @ proj_w^T + proj_b
    gemm128<<<dim3(768 / 128, 8192 / 128), 256>>>(ao, pw, pb, out, 8192, 768, 768);
}

// round 10
// speedup vs baseline: 1.2994x; 1.0091x over previous
#include <cuda_runtime.h>
#include <cstdint>

#define TP 132     // 128-wide tile pitch (words)
#define VP 68      // 64-wide tile pitch (words)

typedef unsigned long long u64t;

// ---------------- packed f32x2 helpers (FFMA2 path, sm_103a) ----------------
__device__ __forceinline__ u64t pk2(float x, float y) {
    u64t r; asm("mov.b64 %0, {%1,%2};" : "=l"(r) : "f"(x), "f"(y)); return r;
}
__device__ __forceinline__ u64t ffma2(u64t a, u64t b, u64t c) {
    u64t d; asm("fma.rn.f32x2 %0, %1, %2, %3;" : "=l"(d) : "l"(a), "l"(b), "l"(c)); return d;
}
__device__ __forceinline__ u64t add2(u64t a, u64t b) {
    u64t d; asm("add.rn.f32x2 %0, %1, %2;" : "=l"(d) : "l"(a), "l"(b)); return d;
}
__device__ __forceinline__ u64t mul2(u64t a, u64t b) {
    u64t d; asm("mul.rn.f32x2 %0, %1, %2;" : "=l"(d) : "l"(a), "l"(b)); return d;
}

// ---------------- tf32 helpers (mma.sync path, sm_80+ so plain sm_103 OK) ----------------
__device__ __forceinline__ uint32_t tf32b(float a) {
    uint32_t u; asm("cvt.rna.tf32.f32 %0, %1;" : "=r"(u) : "f"(a)); return u;
}
__device__ __forceinline__ void mma_tf32(float* d, const uint32_t* a, const uint32_t* b) {
    asm("mma.sync.aligned.m16n8k8.row.col.f32.tf32.tf32.f32 "
        "{%0,%1,%2,%3}, {%4,%5,%6,%7}, {%8,%9}, {%0,%1,%2,%3};"
        : "+f"(d[0]), "+f"(d[1]), "+f"(d[2]), "+f"(d[3])
        : "r"(a[0]), "r"(a[1]), "r"(a[2]), "r"(a[3]), "r"(b[0]), "r"(b[1]));
}

// ---------------- scratch (device globals; no allocation allowed) ----------------
__device__ float g_Y[8192ULL * 2304];      // QKV output (B*N, 3*H*d): t*768 + h*64 + d
__device__ float g_qgr[384ULL * 256 * 64]; // Q-grassmann  [slab][n][d], slab = b*12+h
__device__ float g_kgr[384ULL * 256 * 64];
__device__ float g_attn[384ULL * 256 * 256]; // dots^2*scale, then (in-place) softmaxed attn
__device__ float g_ao[8192ULL * 768];      // attn@V, (b,n,h,d) flattened

// ================= shared smem staging macros (A,B: row-major NxK sources) ==================
#define G128_LDG()                                                                                 \
    a0 = *(const float4*)(Ap + k0);     a1 = *(const float4*)(Ap + k0 + 4);                        \
    b0 = *(const float4*)(Bp + k0);     b1 = *(const float4*)(Bp + k0 + 4);

#define G128_STORE(Ad, Bd)                                                                         \
    Ad[(lk + 0) * TP + lr] = a0.x; Ad[(lk + 1) * TP + lr] = a0.y;                                  \
    Ad[(lk + 2) * TP + lr] = a0.z; Ad[(lk + 3) * TP + lr] = a0.w;                                  \
    Ad[(lk + 4) * TP + lr] = a1.x; Ad[(lk + 5) * TP + lr] = a1.y;                                  \
    Ad[(lk + 6) * TP + lr] = a1.z; Ad[(lk + 7) * TP + lr] = a1.w;                                  \
    Bd[(lk + 0) * TP + lr] = b0.x; Bd[(lk + 1) * TP + lr] = b0.y;                                  \
    Bd[(lk + 2) * TP + lr] = b0.z; Bd[(lk + 3) * TP + lr] = b0.w;                                  \
    Bd[(lk + 4) * TP + lr] = b1.x; Bd[(lk + 5) * TP + lr] = b1.y;                                  \
    Bd[(lk + 6) * TP + lr] = b1.z; Bd[(lk + 7) * TP + lr] = b1.w;

// 3xTF32 fragment compute for one k8 sub-step of a 16-deep buffer.
// qg = lane>>2 (group id), qk = lane&3. Warp tile 64(M) x 32(N): 4 m16 x 4 n8.
#define MMA_K8(Ac, Bc, ks) do {                                                                    \
    uint32_t Ahi[4][4], Alo[4][4], Bhi[4][2], Blo[4][2];                                           \
    _Pragma("unroll")                                                                              \
    for (int i = 0; i < 4; ++i) {                                                                  \
        const float* ap0 = Ac + (ks + qk) * TP + wm0 + 16 * i + qg;                                \
        const float* ap1 = Ac + (ks + 4 + qk) * TP + wm0 + 16 * i + qg;                            \
        float x0 = ap0[0], x1 = ap0[8], x2 = ap1[0], x3 = ap1[8];                                  \
        Ahi[i][0] = tf32b(x0); Alo[i][0] = tf32b(x0 - __uint_as_float(Ahi[i][0]));                 \
        Ahi[i][1] = tf32b(x1); Alo[i][1] = tf32b(x1 - __uint_as_float(Ahi[i][1]));                 \
        Ahi[i][2] = tf32b(x2); Alo[i][2] = tf32b(x2 - __uint_as_float(Ahi[i][2]));                 \
        Ahi[i][3] = tf32b(x3); Alo[i][3] = tf32b(x3 - __uint_as_float(Ahi[i][3]));                 \
    }                                                                                              \
    _Pragma("unroll")                                                                              \
    for (int j = 0; j < 4; ++j) {                                                                  \
        float y0 = Bc[(ks + qk) * TP + wn0 + 8 * j + qg];                                          \
        float y1 = Bc[(ks + 4 + qk) * TP + wn0 + 8 * j + qg];                                      \
        Bhi[j][0] = tf32b(y0); Blo[j][0] = tf32b(y0 - __uint_as_float(Bhi[j][0]));                 \
        Bhi[j][1] = tf32b(y1); Blo[j][1] = tf32b(y1 - __uint_as_float(Bhi[j][1]));                 \
    }                                                                                              \
    _Pragma("unroll")                                                                              \
    for (int i = 0; i < 4; ++i)                                                                    \
        _Pragma("unroll")                                                                          \
        for (int j = 0; j < 4; ++j) {                                                              \
            mma_tf32(acc[i][j], Ahi[i], Bhi[j]);                                                   \
            mma_tf32(acc[i][j], Ahi[i], Blo[j]);                                                   \
            mma_tf32(acc[i][j], Alo[i], Bhi[j]);                                                   \
        }                                                                                          \
} while (0)

// ---------------- C = A @ B^T + bias via mma.sync 3xTF32 (128x128 tile, BK=16 dbuf) ----------
__global__ __launch_bounds__(256, 1) void gemm_mma(const float* __restrict__ A,
                                                   const float* __restrict__ B,
                                                   const float* __restrict__ bias,
                                                   float* __restrict__ C,
                                                   int M, int N, int K)
{
    __shared__ float As[2][16 * TP];
    __shared__ float Bs[2][16 * TP];
    const int n0 = blockIdx.x * 128;
    const int m0 = blockIdx.y * 128;
    const int t  = threadIdx.x;
    const int w  = t >> 5, lane = t & 31;
    const int qg = lane >> 2, qk = lane & 3;
    const int wm0 = (w & 1) * 64;      // warp M offset within tile
    const int wn0 = (w >> 1) * 32;     // warp N offset within tile
    const int lr = t >> 1, lk = (t & 1) * 8;
    const float* Ap = A + (size_t)(m0 + lr) * K + lk;
    const float* Bp = B + (size_t)(n0 + lr) * K + lk;

    float acc[4][4][4] = {};
    float4 a0, a1, b0, b1;
    int k0 = 0;
    G128_LDG()
    { float* Ad = As[0]; float* Bd = Bs[0]; G128_STORE(Ad, Bd) }
    __syncthreads();
    int buf = 0;
    for (k0 = 16; k0 < K; k0 += 16) {
        G128_LDG()
        {
            const float* Ac = As[buf]; const float* Bc = Bs[buf];
            MMA_K8(Ac, Bc, 0);
            MMA_K8(Ac, Bc, 8);
        }
        { float* Ad = As[buf ^ 1]; float* Bd = Bs[buf ^ 1]; G128_STORE(Ad, Bd) }
        __syncthreads();
        buf ^= 1;
    }
    {
        const float* Ac = As[buf]; const float* Bc = Bs[buf];
        MMA_K8(Ac, Bc, 0);
        MMA_K8(Ac, Bc, 8);
    }

    // epilogue: acc tile (i,j): rows m0+wm0+16i+{qg, qg+8}, cols n0+wn0+8j+2qk..+1
#pragma unroll
    for (int j = 0; j < 4; ++j) {
        const int c = n0 + wn0 + 8 * j + 2 * qk;
        float2 bb = *(const float2*)(bias + c);
#pragma unroll
        for (int i = 0; i < 4; ++i) {
            const int r0 = m0 + wm0 + 16 * i + qg;
            float2 o0, o1;
            o0.x = acc[i][j][0] + bb.x; o0.y = acc[i][j][1] + bb.y;
            o1.x = acc[i][j][2] + bb.x; o1.y = acc[i][j][3] + bb.y;
            *(float2*)(C + (size_t)r0 * N + c)       = o0;
            *(float2*)(C + (size_t)(r0 + 8) * N + c) = o1;
        }
    }
}

// ---------------- per-slab dots = Qgr @ Kgr^T, fused square * scale (FFMA2) ----------------
#define G128_COMP(Ac, Bc)                                                                          \
    _Pragma("unroll")                                                                              \
    for (int kk = 0; kk < 16; ++kk) {                                                              \
        float4 av0 = *(const float4*)(Ac + kk * TP + ty * 8);                                      \
        float4 av1 = *(const float4*)(Ac + kk * TP + ty * 8 + 4);                                  \
        ulonglong2 bL = *(const ulonglong2*)(Bc + kk * TP + tx * 4);                               \
        ulonglong2 bR = *(const ulonglong2*)(Bc + kk * TP + 64 + tx * 4);                          \
        float ar[8] = {av0.x, av0.y, av0.z, av0.w, av1.x, av1.y, av1.z, av1.w};                    \
        _Pragma("unroll")                                                                          \
        for (int i = 0; i < 8; ++i) {                                                              \
            u64t aa = pk2(ar[i], ar[i]);                                                           \
            acc2[i][0] = ffma2(aa, bL.x, acc2[i][0]);                                              \
            acc2[i][1] = ffma2(aa, bL.y, acc2[i][1]);                                              \
            acc2[i][2] = ffma2(aa, bR.x, acc2[i][2]);                                              \
            acc2[i][3] = ffma2(aa, bR.y, acc2[i][3]);                                              \
        }                                                                                          \
    }

__global__ __launch_bounds__(256, 2) void dots128(const float* __restrict__ Qg,
                                                  const float* __restrict__ Kg,
                                                  float* __restrict__ G,
                                                  const float* __restrict__ scale_p)
{
    __shared__ float As[2][16 * TP];
    __shared__ float Bs[2][16 * TP];
    const int slab = blockIdx.z;
    const int m0 = blockIdx.x * 128;
    const int n0 = blockIdx.y * 128;
    const int t  = threadIdx.x;
    const int tx = t & 15, ty = t >> 4;
    const int lr = t >> 1, lk = (t & 1) * 8;
    const float* Ap = Qg + (size_t)slab * 256 * 64 + (size_t)(n0 + lr) * 64 + lk;
    const float* Bp = Kg + (size_t)slab * 256 * 64 + (size_t)(m0 + lr) * 64 + lk;
    u64t acc2[8][4] = {};
    float4 a0, a1, b0, b1;
    int k0 = 0;
    G128_LDG()
    { float* Ad = As[0]; float* Bd = Bs[0]; G128_STORE(Ad, Bd) }
    __syncthreads();
    int buf = 0;
    for (k0 = 16; k0 < 64; k0 += 16) {
        G128_LDG()
        { const float* Ac = As[buf]; const float* Bc = Bs[buf]; G128_COMP(Ac, Bc) }
        { float* Ad = As[buf ^ 1]; float* Bd = Bs[buf ^ 1]; G128_STORE(Ad, Bd) }
        __syncthreads();
        buf ^= 1;
    }
    { const float* Ac = As[buf]; const float* Bc = Bs[buf]; G128_COMP(Ac, Bc) }

    const float sc = *scale_p;
    const u64t scp = pk2(sc, sc);
#pragma unroll
    for (int i = 0; i < 8; ++i) {
        float* gp = G + ((size_t)slab * 256 + n0 + ty * 8 + i) * 256 + m0 + tx * 4;
        ulonglong2 s0, s1;
        s0.x = mul2(mul2(acc2[i][0], acc2[i][0]), scp);
        s0.y = mul2(mul2(acc2[i][1], acc2[i][1]), scp);
        s1.x = mul2(mul2(acc2[i][2], acc2[i][2]), scp);
        s1.y = mul2(mul2(acc2[i][3], acc2[i][3]), scp);
        *(ulonglong2*)gp        = s0;
        *(ulonglong2*)(gp + 64) = s1;
    }
}

// ---------------- per-slab Householder QR (LAPACK convention), Q via org2r ----------------
__global__ void qr_kernel(const float* __restrict__ Y, float* __restrict__ Qq,
                          float* __restrict__ Qk)
{
    extern __shared__ float A[];   // 64 * 257 floats
    __shared__ float tauv[64];
    __shared__ float red[8];
    __shared__ float s_tau, s_inv;
    const int bid = blockIdx.x;
    const int slab = (bid < 384) ? bid : bid - 384;
    const int coloff = (bid < 384) ? 0 : 768;
    float* Qout = (bid < 384) ? Qq : Qk;
    const int b = slab / 12, h = slab % 12;
    const float* src = Y + (size_t)b * 256 * 2304 + coloff + h * 64;
    const int t = threadIdx.x;
    const int lane = t & 31, wid = t >> 5;

    {   // load 256x64, store transposed (column-major)
        const int rloc = t >> 4, dg = (t & 15) << 2;
#pragma unroll
        for (int it = 0; it < 16; ++it) {
            int n = it * 16 + rloc;
            float4 v = *(const float4*)(src + (size_t)n * 2304 + dg);
            A[(dg + 0) * 257 + n] = v.x;
            A[(dg + 1) * 257 + n] = v.y;
            A[(dg + 2) * 257 + n] = v.z;
            A[(dg + 3) * 257 + n] = v.w;
        }
    }
    __syncthreads();

    // -------- geqf2 (unblocked Householder) --------
    for (int j = 0; j < 64; ++j) {
        float p = 0.f;
        if (t > j) { float x = A[j * 257 + t]; p = x * x; }
#pragma unroll
        for (int o = 16; o; o >>= 1) p += __shfl_xor_sync(0xffffffffu, p, o);
        if (lane == 0) red[wid] = p;
        __syncthreads();
        if (t == 0) {
            float xn2 = red[0] + red[1] + red[2] + red[3] + red[4] + red[5] + red[6] + red[7];
            float alpha = A[j * 257 + j];
            float tau, inv;
            if (xn2 <= 0.f) { tau = 0.f; inv = 0.f; }
            else {
                float nrm  = sqrtf(alpha * alpha + xn2);
                float beta = (alpha >= 0.f) ? -nrm : nrm;  // LAPACK dlarfg sign
                tau = (beta - alpha) / beta;
                inv = 1.f / (alpha - beta);
            }
            tauv[j] = tau; s_tau = tau; s_inv = inv;
        }
        __syncthreads();
        float tau = s_tau;
        if (t > j) A[j * 257 + t] *= s_inv;   // v (v0=1 implicit)
        __syncthreads();
        float vr[8];
#pragma unroll
        for (int r = 0; r < 8; ++r) {
            int i = j + lane + 32 * r;
            vr[r] = (i < 256) ? ((i == j) ? 1.f : A[j * 257 + i]) : 0.f;
        }
        for (int k = j + 1 + wid; k < 64; k += 8) {
            float s = 0.f, ar[8];
#pragma unroll
            for (int r = 0; r < 8; ++r) {
                int i = j + lane + 32 * r;
                ar[r] = (i < 256) ? A[k * 257 + i] : 0.f;
                s += vr[r] * ar[r];
            }
#pragma unroll
            for (int o = 16; o; o >>= 1) s += __shfl_xor_sync(0xffffffffu, s, o);
            float ts = tau * s;
#pragma unroll
            for (int r = 0; r < 8; ++r) {
                int i = j + lane + 32 * r;
                if (i < 256) A[k * 257 + i] = ar[r] - ts * vr[r];
            }
        }
        __syncthreads();
    }

    // -------- org2r: form Q in place (backward accumulation) --------
    for (int j = 63; j >= 0; --j) {
        float tau = tauv[j];
        float vr[8];
#pragma unroll
        for (int r = 0; r < 8; ++r) {
            int i = j + lane + 32 * r;
            vr[r] = (i < 256) ? ((i == j) ? 1.f : A[j * 257 + i]) : 0.f;
        }
        for (int k = j + 1 + wid; k < 64; k += 8) {
            float s = 0.f, ar[8];
#pragma unroll
            for (int r = 0; r < 8; ++r) {
                int i = j + lane + 32 * r;
                ar[r] = (i < 256) ? A[k * 257 + i] : 0.f;
                s += vr[r] * ar[r];
            }
#pragma unroll
            for (int o = 16; o; o >>= 1) s += __shfl_xor_sync(0xffffffffu, s, o);
            float ts = tau * s;
#pragma unroll
            for (int r = 0; r < 8; ++r) {
                int i = j + lane + 32 * r;
                if (i < 256) A[k * 257 + i] = ar[r] - ts * vr[r];
            }
        }
        __syncthreads();
        {
            float val;
            if (t < j)       val = 0.f;
            else if (t == j) val = 1.f - tau;
            else             val = -tau * A[j * 257 + t];
            A[j * 257 + t] = val;
        }
        __syncthreads();
    }

    {   // store Q packed [slab][n][d]
        const int rloc = t >> 4, dg = (t & 15) << 2;
#pragma unroll
        for (int it = 0; it < 16; ++it) {
            int n = it * 16 + rloc;
            float4 v;
            v.x = A[(dg + 0) * 257 + n];
            v.y = A[(dg + 1) * 257 + n];
            v.z = A[(dg + 2) * 257 + n];
            v.w = A[(dg + 3) * 257 + n];
            *(float4*)(Qout + ((size_t)slab * 256 + n) * 64 + dg) = v;
        }
    }
}

// ---------------- cross-head 1x1-conv mix + softmax, in place on G ----------------
__global__ void mix_softmax(float* __restrict__ G, const float* __restrict__ cw,
                            const float* __restrict__ cbg)
{
    __shared__ float gsm[12 * 256];
    __shared__ float w2[144];
    __shared__ float cb[12];
    const int n = blockIdx.x, b = blockIdx.y;
    const int t = threadIdx.x;          // 384
    const int lane = t & 31, wo = t >> 5;
    if (t < 144) { int o = t / 12, h = t % 12; w2[t] = cw[o * 24 + h] + cw[o * 24 + 12 + h]; }
    if (t < 12) cb[t] = cbg[t];
    {
        float* dstp = gsm + wo * 256;
        const float* srcp = G + ((size_t)(b * 12 + wo) * 256 + n) * 256;
        *(float4*)(dstp + lane * 4)       = *(const float4*)(srcp + lane * 4);
        *(float4*)(dstp + 128 + lane * 4) = *(const float4*)(srcp + 128 + lane * 4);
    }
    __syncthreads();
    float vals[8];
    float mx = -3.4e38f;
#pragma unroll
    for (int r = 0; r < 8; ++r) {
        int m = lane + 32 * r;
        float s = cb[wo];
#pragma unroll
        for (int h = 0; h < 12; ++h) s += w2[wo * 12 + h] * gsm[h * 256 + m];
        vals[r] = s;
        mx = fmaxf(mx, s);
    }
#pragma unroll
    for (int o = 16; o; o >>= 1) mx = fmaxf(mx, __shfl_xor_sync(0xffffffffu, mx, o));
    float sum = 0.f;
#pragma unroll
    for (int r = 0; r < 8; ++r) { vals[r] = expf(vals[r] - mx); sum += vals[r]; }
#pragma unroll
    for (int o = 16; o; o >>= 1) sum += __shfl_xor_sync(0xffffffffu, sum, o);
    float inv = 1.f / sum;
    float* dst = G + ((size_t)(b * 12 + wo) * 256 + n) * 256;
#pragma unroll
    for (int r = 0; r < 8; ++r) dst[lane + 32 * r] = vals[r] * inv;
}

// ---------------- out_h = attn @ v  (128x64 tile, 8x4/thread packed, double-buffered) ---------
__global__ __launch_bounds__(256, 2) void attnv128(const float* __restrict__ Attn,
                                                   const float* __restrict__ Y,
                                                   float* __restrict__ AO)
{
    __shared__ float As[2][16 * TP];  // [kk][n-row], transposed attn tile
    __shared__ float Bs[2][16 * VP];  // [kk][d]
    const int slab = blockIdx.y;
    const int b = slab / 12, h = slab % 12;
    const int n0 = blockIdx.x * 128;
    const float* Ap = Attn + (size_t)slab * 256 * 256;
    const float* Vp = Y + (size_t)b * 256 * 2304 + 1536 + h * 64;
    const int t = threadIdx.x;
    const int tx = t & 15, ty = t >> 4;
    const int ar = t >> 2, ag = (t & 3) << 2;   // attn: rows ar, ar+64; cols ag..ag+3
    const int vr = t >> 4, vg = (t & 15) << 2;  // V: row vr; cols vg..vg+3
    u64t acc2[8][2] = {};
    float4 a0, a1, v0;
    int m0 = 0;
    a0 = *(const float4*)(Ap + (size_t)(n0 + ar) * 256 + m0 + ag);
    a1 = *(const float4*)(Ap + (size_t)(n0 + 64 + ar) * 256 + m0 + ag);
    v0 = *(const float4*)(Vp + (size_t)(m0 + vr) * 2304 + vg);
    {
        float* Ad = As[0]; float* Bd = Bs[0];
        Ad[(ag + 0) * TP + ar] = a0.x; Ad[(ag + 1) * TP + ar] = a0.y;
        Ad[(ag + 2) * TP + ar] = a0.z; Ad[(ag + 3) * TP + ar] = a0.w;
        Ad[(ag + 0) * TP + 64 + ar] = a1.x; Ad[(ag + 1) * TP + 64 + ar] = a1.y;
        Ad[(ag + 2) * TP + 64 + ar] = a1.z; Ad[(ag + 3) * TP + 64 + ar] = a1.w;
        *(float4*)(Bd + vr * VP + vg) = v0;
    }
    __syncthreads();
    int buf = 0;
    for (m0 = 16; m0 < 256; m0 += 16) {
        a0 = *(const float4*)(Ap + (size_t)(n0 + ar) * 256 + m0 + ag);
        a1 = *(const float4*)(Ap + (size_t)(n0 + 64 + ar) * 256 + m0 + ag);
        v0 = *(const float4*)(Vp + (size_t)(m0 + vr) * 2304 + vg);
        {
            const float* Ac = As[buf]; const float* Bc = Bs[buf];
#pragma unroll
            for (int kk = 0; kk < 16; ++kk) {
                float4 av0 = *(const float4*)(Ac + kk * TP + ty * 8);
                float4 av1 = *(const float4*)(Ac + kk * TP + ty * 8 + 4);
                ulonglong2 bb = *(const ulonglong2*)(Bc + kk * VP + tx * 4);
                float arr[8] = {av0.x, av0.y, av0.z, av0.w, av1.x, av1.y, av1.z, av1.w};
#pragma unroll
                for (int i = 0; i < 8; ++i) {
                    u64t aa = pk2(arr[i], arr[i]);
                    acc2[i][0] = ffma2(aa, bb.x, acc2[i][0]);
                    acc2[i][1] = ffma2(aa, bb.y, acc2[i][1]);
                }
            }
        }
        {
            float* Ad = As[buf ^ 1]; float* Bd = Bs[buf ^ 1];
            Ad[(ag + 0) * TP + ar] = a0.x; Ad[(ag + 1) * TP + ar] = a0.y;
            Ad[(ag + 2) * TP + ar] = a0.z; Ad[(ag + 3) * TP + ar] = a0.w;
            Ad[(ag + 0) * TP + 64 + ar] = a1.x; Ad[(ag + 1) * TP + 64 + ar] = a1.y;
            Ad[(ag + 2) * TP + 64 + ar] = a1.z; Ad[(ag + 3) * TP + 64 + ar] = a1.w;
            *(float4*)(Bd + vr * VP + vg) = v0;
        }
        __syncthreads();
        buf ^= 1;
    }
    {
        const float* Ac = As[buf]; const float* Bc = Bs[buf];
#pragma unroll
        for (int kk = 0; kk < 16; ++kk) {
            float4 av0 = *(const float4*)(Ac + kk * TP + ty * 8);
            float4 av1 = *(const float4*)(Ac + kk * TP + ty * 8 + 4);
            ulonglong2 bb = *(const ulonglong2*)(Bc + kk * VP + tx * 4);
            float arr[8] = {av0.x, av0.y, av0.z, av0.w, av1.x, av1.y, av1.z, av1.w};
#pragma unroll
            for (int i = 0; i < 8; ++i) {
                u64t aa = pk2(arr[i], arr[i]);
                acc2[i][0] = ffma2(aa, bb.x, acc2[i][0]);
                acc2[i][1] = ffma2(aa, bb.y, acc2[i][1]);
            }
        }
    }
#pragma unroll
    for (int i = 0; i < 8; ++i) {
        ulonglong2 s;
        s.x = acc2[i][0]; s.y = acc2[i][1];
        *(ulonglong2*)(AO + (size_t)(b * 256 + n0 + ty * 8 + i) * 768 + h * 64 + tx * 4) = s;
    }
}

// ---------------- launch ----------------
extern "C" void kernel_launch(void* const* d_in, const int* in_sizes, int n_in,
                              void* d_out, int out_size)
{
    (void)in_sizes; (void)n_in; (void)out_size;
    const float* x    = (const float*)d_in[0];
    const float* qkvw = (const float*)d_in[1];
    const float* qkvb = (const float*)d_in[2];
    const float* gsc  = (const float*)d_in[3];
    const float* cw   = (const float*)d_in[4];
    const float* cb   = (const float*)d_in[5];
    const float* pw   = (const float*)d_in[6];
    const float* pb   = (const float*)d_in[7];
    float* out = (float*)d_out;

    float *Y, *qgr, *kgr, *attn, *ao;
    cudaGetSymbolAddress((void**)&Y, g_Y);
    cudaGetSymbolAddress((void**)&qgr, g_qgr);
    cudaGetSymbolAddress((void**)&kgr, g_kgr);
    cudaGetSymbolAddress((void**)&attn, g_attn);
    cudaGetSymbolAddress((void**)&ao, g_ao);

    cudaFuncSetAttribute(qr_kernel, cudaFuncAttributeMaxDynamicSharedMemorySize, 64 * 257 * 4);

    // 1) QKV: Y = x @ qkv_w^T + qkv_b   (8192 x 2304, K=768) — mma.sync 3xTF32
    gemm_mma<<<dim3(2304 / 128, 8192 / 128), 256>>>(x, qkvw, qkvb, Y, 8192, 2304, 768);
    // 2) Householder QR per (b,h) slab for q AND k in one launch (768 blocks)
    qr_kernel<<<768, 256, 64 * 257 * 4>>>(Y, qgr, kgr);
    // 3) dots^2 * scale per slab (128x128 tiles)
    dots128<<<dim3(2, 2, 384), 256>>>(qgr, kgr, attn, gsc);
    // 4) cross-head mix + softmax (in place)
    mix_softmax<<<dim3(256, 32), 384>>>(attn, cw, cb);
    // 5) attn @ v  -> (b,n,h*64+d)
    attnv128<<<dim3(2, 384), 256>>>(attn, Y, ao);
    // 6) proj: out = ao @ proj_w^T + proj_b — mma.sync 3xTF32
    gemm_mma<<<dim3(768 / 128, 8192 / 128), 256>>>(ao, pw, pb, out, 8192, 768, 768);
}